// round 15
// baseline (speedup 1.0000x reference)
#include <cuda_runtime.h>
#include <cuda_fp16.h>
#include <cuda_bf16.h>
#include <cstdint>

#define NODES   10000
#define EDGES   320000
#define HIDC    128
#define NGAUSS  50
#define NBLK    6

#define NPC     72     // nodes per CTA in fused GEMM kernel (512 thr, 8 grp x 9)
#define GNP     9      // nodes per thread-group

#define GDELTA  (10.0f / 49.0f)
#define GCOEFF  (-0.5f / (GDELTA * GDELTA))

#define TROWS   3072                     // filter table rows
#define DMAX    8.66025404f              // max possible d (box 5^3)
#define TSCALE  ((TROWS - 1) / DMAX)
#define DSTEP   (DMAX / (TROWS - 1))

// ---------------- scratch (device globals; no runtime allocation) ----------
__device__ float  g_h[NODES * HIDC];
__device__ __align__(16) __half g_xh[NODES * HIDC];   // x in fp16 (message path)
__device__ float  g_agg[NODES * HIDC];
__device__ float  g_embx[100 * HIDC];                 // emb @ cl1[0]

// CSR by target node + per-edge interp metadata
__device__ int  g_cnt[NODES];
__device__ int  g_rank[EDGES];
__device__ int  g_ptr[NODES + 1];
__device__ __align__(16) int4 g_meta[EDGES];   // {row, tbase, w0_bits, w1_bits}

// filter tables in fp16: W_k(d) on TROWS points, [TROWS][128] per block
__device__ __align__(16) __half g_tableh[NBLK][TROWS * HIDC];

// pre-split bf16 hi/lo weight images, padded row-major [ch][Kpad]
__device__ __align__(16) uint32_t g_w1h[NBLK][4608];
__device__ __align__(16) uint32_t g_w1l[NBLK][4608];
__device__ __align__(16) uint32_t g_w2h[NBLK][8704];
__device__ __align__(16) uint32_t g_w2l[NBLK][8704];

// ---------------- helpers ---------------------------------------------------
using ull = unsigned long long;

__device__ __forceinline__ uint32_t smem_u32(const void* p) {
    uint32_t a;
    asm("{ .reg .u64 t; cvta.to.shared.u64 t, %1; cvt.u32.u64 %0, t; }" : "=r"(a) : "l"(p));
    return a;
}
#define CP16(s, g) asm volatile("cp.async.cg.shared.global [%0], [%1], 16;" :: "r"(s), "l"(g))
#define CP_COMMIT() asm volatile("cp.async.commit_group;" ::: "memory")
#define CP_WAIT(n)  asm volatile("cp.async.wait_group %0;" :: "n"(n) : "memory")

__device__ __forceinline__ void ldsm_x4(uint32_t* r, uint32_t addr) {
    asm volatile("ldmatrix.sync.aligned.m8n8.x4.shared.b16 {%0,%1,%2,%3}, [%4];"
                 : "=r"(r[0]), "=r"(r[1]), "=r"(r[2]), "=r"(r[3]) : "r"(addr));
}
__device__ __forceinline__ void ldsm_x2(uint32_t* r, uint32_t addr) {
    asm volatile("ldmatrix.sync.aligned.m8n8.x2.shared.b16 {%0,%1}, [%2];"
                 : "=r"(r[0]), "=r"(r[1]) : "r"(addr));
}
__device__ __forceinline__ void mma_bf16(float* c, const uint32_t* a, const uint32_t* b) {
    asm volatile("mma.sync.aligned.m16n8k16.row.col.f32.bf16.bf16.f32 "
                 "{%0,%1,%2,%3}, {%4,%5,%6,%7}, {%8,%9}, {%0,%1,%2,%3};"
                 : "+f"(c[0]), "+f"(c[1]), "+f"(c[2]), "+f"(c[3])
                 : "r"(a[0]), "r"(a[1]), "r"(a[2]), "r"(a[3]), "r"(b[0]), "r"(b[1]));
}
__device__ __forceinline__ uint32_t bfpair(float f0, float f1) {
    uint32_t r;
    asm("cvt.rn.bf16x2.f32 %0, %1, %2;" : "=r"(r) : "f"(f1), "f"(f0));
    return r;
}
__device__ __forceinline__ void bfsplit(float f0, float f1, uint32_t& hi, uint32_t& lo) {
    hi = bfpair(f0, f1);
    float h0 = __uint_as_float(hi << 16);
    float h1 = __uint_as_float(hi & 0xFFFF0000u);
    lo = bfpair(f0 - h0, f1 - h1);
}
__device__ __forceinline__ float sspf(float v) {
    float t, u;
    asm("ex2.approx.f32 %0, %1;" : "=f"(t) : "f"(v * 1.4426950408889634f));
    asm("lg2.approx.f32 %0, %1;" : "=f"(u) : "f"(fmaf(0.5f, t, 0.5f)));
    return 0.6931471805599453f * u;
}
__device__ __forceinline__ ull pack2(float a, float b) {
    ull r; asm("mov.b64 %0, {%1, %2};" : "=l"(r) : "f"(a), "f"(b)); return r;
}
__device__ __forceinline__ void unpack2(ull v, float& a, float& b) {
    asm("mov.b64 {%0, %1}, %2;" : "=f"(a), "=f"(b) : "l"(v));
}
__device__ __forceinline__ ull fma2(ull a, ull b, ull c) {
    ull r; asm("fma.rn.f32x2 %0, %1, %2, %3;" : "=l"(r) : "l"(a), "l"(b), "l"(c));
    return r;
}

// ---------------- weight prep + zero CSR counters + embx --------------------
__global__ void k_wprep(const float* __restrict__ mw1, const float* __restrict__ mw2,
                        const float* __restrict__ emb, const float* __restrict__ cl1) {
    const int k = blockIdx.x;
    for (int i = blockIdx.x * blockDim.x + threadIdx.x; i < NODES; i += gridDim.x * blockDim.x)
        g_cnt[i] = 0;
    if (k == NBLK) {
        // embx = emb @ cl1[0]  (100 x 128)
        for (int o = threadIdx.x; o < 100 * HIDC; o += blockDim.x) {
            int r = o >> 7, c = o & 127;
            float s = 0.f;
            #pragma unroll 4
            for (int kk = 0; kk < HIDC; kk++) s += emb[r * HIDC + kk] * cl1[kk * HIDC + c];
            g_embx[o] = s;
        }
        return;
    }
    const float* w1 = mw1 + k * NGAUSS * HIDC;
    const float* w2 = mw2 + k * HIDC * HIDC;
    for (int i = threadIdx.x; i < 4608; i += blockDim.x) {
        int c = i / 36, kk = (i % 36) * 2;
        float v0 = (kk     < NGAUSS) ? w1[kk * HIDC + c]       : 0.f;
        float v1 = (kk + 1 < NGAUSS) ? w1[(kk + 1) * HIDC + c] : 0.f;
        uint32_t hi, lo; bfsplit(v0, v1, hi, lo);
        g_w1h[k][i] = hi; g_w1l[k][i] = lo;
    }
    for (int i = threadIdx.x; i < 8704; i += blockDim.x) {
        int c = i / 68, kk = (i % 68) * 2;
        float v0 = (kk     < HIDC) ? w2[kk * HIDC + c]       : 0.f;
        float v1 = (kk + 1 < HIDC) ? w2[(kk + 1) * HIDC + c] : 0.f;
        uint32_t hi, lo; bfsplit(v0, v1, hi, lo);
        g_w2h[k][i] = hi; g_w2l[k][i] = lo;
    }
}

// ---------------- embedding gather + CSR count + x0 gather ------------------
__global__ void k_embed(const int* __restrict__ z, const float* __restrict__ emb,
                        const int* __restrict__ col) {
    int i = blockIdx.x * blockDim.x + threadIdx.x;
    if (i < EDGES) g_rank[i] = atomicAdd(&g_cnt[col[i]], 1);
    if (i >= NODES * HIDC) return;
    int zi = z[i >> 7] * HIDC + (i & 127);
    g_h[i]  = emb[zi];
    g_xh[i] = __float2half(g_embx[zi]);   // x0 = h @ cl1[0] via precomputed embx
}

// ---------------- CSR scan ----------------------------------------------------
__global__ void k_scan() {   // single block, 1024 threads, chunk=10
    __shared__ int s[1024];
    const int t = threadIdx.x;
    const int base = t * 10;
    int local[10];
    int sum = 0;
    #pragma unroll
    for (int i = 0; i < 10; i++) {
        int idx = base + i;
        local[i] = (idx < NODES) ? g_cnt[idx] : 0;
        sum += local[i];
    }
    s[t] = sum;
    __syncthreads();
    for (int off = 1; off < 1024; off <<= 1) {
        int v = (t >= off) ? s[t - off] : 0;
        __syncthreads();
        s[t] += v;
        __syncthreads();
    }
    int run = (t > 0) ? s[t - 1] : 0;
    #pragma unroll
    for (int i = 0; i < 10; i++) {
        int idx = base + i;
        if (idx < NODES) { g_ptr[idx] = run; run += local[i]; }
    }
    if (t == 1023) g_ptr[NODES] = s[1023];
}
__global__ void k_fill(const float* __restrict__ pos,
                       const int* __restrict__ row, const int* __restrict__ col) {
    int e = blockIdx.x * blockDim.x + threadIdx.x;
    if (e >= EDGES) return;
    int r = row[e], c = col[e];
    float dx = pos[r * 3 + 0] - pos[c * 3 + 0];
    float dy = pos[r * 3 + 1] - pos[c * 3 + 1];
    float dz = pos[r * 3 + 2] - pos[c * 3 + 2];
    float d = sqrtf(dx * dx + dy * dy + dz * dz);
    float C = 0.5f * (cosf(d * (3.14159265358979323846f / 10.0f)) + 1.0f);
    int pos_ = g_ptr[c] + g_rank[e];
    float fidx = d * TSCALE;
    int tb = (int)fidx;
    if (tb > TROWS - 2) tb = TROWS - 2;
    float fr = fidx - (float)tb;
    int4 m;
    m.x = r;
    m.y = tb;
    m.z = __float_as_int((1.0f - fr) * C);
    m.w = __float_as_int(fr * C);
    g_meta[pos_] = m;
}

// ---------------- table build: MMA filter MLP on TROWS d-samples -------------
#define S_W1H 0
#define S_W1L 18432
#define S_W2H 36864
#define S_W2L 71680
#define S_AH  106496
#define S_AL  141312
#define FILT_SMEM 176128

__global__ void __launch_bounds__(256, 1)
k_tbuild(const float* __restrict__ mb1, const float* __restrict__ mb2) {
    extern __shared__ __align__(16) unsigned char sraw[];
    const uint32_t sb = smem_u32(sraw);
    const int tid  = threadIdx.x;
    const int wid  = tid >> 5;
    const int lan  = tid & 31;
    const int kblk = blockIdx.y;
    const int e0   = blockIdx.x * 128;
    const float* b1g = mb1 + kblk * HIDC;
    const float* b2g = mb2 + kblk * HIDC;

    {
        const int4* s1h = (const int4*)g_w1h[kblk];
        const int4* s1l = (const int4*)g_w1l[kblk];
        const int4* s2h = (const int4*)g_w2h[kblk];
        const int4* s2l = (const int4*)g_w2l[kblk];
        int4* d1h = (int4*)(sraw + S_W1H);
        int4* d1l = (int4*)(sraw + S_W1L);
        int4* d2h = (int4*)(sraw + S_W2H);
        int4* d2l = (int4*)(sraw + S_W2L);
        #pragma unroll 2
        for (int i = tid; i < 1152; i += 256) { d1h[i] = s1h[i]; d1l[i] = s1l[i]; }
        #pragma unroll 4
        for (int i = tid; i < 2176; i += 256) { d2h[i] = s2h[i]; d2l[i] = s2l[i]; }
    }

    for (int i = tid; i < 128 * 36; i += 256) {
        int e = i / 36, kk = (i % 36) * 2;
        float d = (float)(e0 + e) * DSTEP;
        float v0 = 0.f, v1 = 0.f;
        if (kk < NGAUSS)     { float dd = d - (float)kk * GDELTA;       v0 = __expf(GCOEFF * dd * dd); }
        if (kk + 1 < NGAUSS) { float dd = d - (float)(kk + 1) * GDELTA; v1 = __expf(GCOEFF * dd * dd); }
        uint32_t hi, lo; bfsplit(v0, v1, hi, lo);
        *(uint32_t*)(sraw + S_AH + e * 144 + kk * 2) = hi;
        *(uint32_t*)(sraw + S_AL + e * 144 + kk * 2) = lo;
    }
    __syncthreads();

    const uint32_t aoff1 = (lan & 15) * 144 + (lan >> 4) * 16;
    const uint32_t boff1 = (wid * 16 + (lan & 7)) * 144 + ((lan >> 3) & 1) * 16;
    const uint32_t aoff2 = (lan & 15) * 272 + (lan >> 4) * 16;
    const uint32_t boff2 = (wid * 16 + (lan & 7)) * 272 + ((lan >> 3) & 1) * 16;

    float acc[8][2][4];

    // layer 1
    #pragma unroll
    for (int mt = 0; mt < 8; mt++)
        #pragma unroll
        for (int nt = 0; nt < 2; nt++)
            #pragma unroll
            for (int i = 0; i < 4; i++) acc[mt][nt][i] = 0.f;
    {
        const uint32_t ab[3] = { sb + S_AH + aoff1, sb + S_AH + aoff1, sb + S_AL + aoff1 };
        const uint32_t bb[3] = { sb + S_W1H + boff1, sb + S_W1L + boff1, sb + S_W1H + boff1 };
        #pragma unroll 1
        for (int t = 0; t < 3; t++) {
            #pragma unroll 1
            for (int ks = 0; ks < 4; ks++) {
                uint32_t bf0[2], bf1[2];
                ldsm_x2(bf0, bb[t] + ks * 32);
                ldsm_x2(bf1, bb[t] + 8 * 144 + ks * 32);
                #pragma unroll
                for (int mt = 0; mt < 8; mt++) {
                    uint32_t af[4];
                    ldsm_x4(af, ab[t] + mt * (16 * 144) + ks * 32);
                    mma_bf16(acc[mt][0], af, bf0);
                    mma_bf16(acc[mt][1], af, bf1);
                }
            }
        }
    }
    __syncthreads();

    // epilogue 1
    {
        const int ch0 = wid * 16 + (lan & 3) * 2;
        const float bA0 = b1g[ch0],     bA1 = b1g[ch0 + 1];
        const float bA2 = b1g[ch0 + 8], bA3 = b1g[ch0 + 9];
        #pragma unroll
        for (int mt = 0; mt < 8; mt++) {
            int er = mt * 16 + (lan >> 2);
            uint32_t hi, lo;
            float v0 = sspf(acc[mt][0][0] + bA0), v1 = sspf(acc[mt][0][1] + bA1);
            bfsplit(v0, v1, hi, lo);
            *(uint32_t*)(sraw + S_AH + er * 272 + ch0 * 2) = hi;
            *(uint32_t*)(sraw + S_AL + er * 272 + ch0 * 2) = lo;
            float v2 = sspf(acc[mt][0][2] + bA0), v3 = sspf(acc[mt][0][3] + bA1);
            bfsplit(v2, v3, hi, lo);
            *(uint32_t*)(sraw + S_AH + (er + 8) * 272 + ch0 * 2) = hi;
            *(uint32_t*)(sraw + S_AL + (er + 8) * 272 + ch0 * 2) = lo;
            float v4 = sspf(acc[mt][1][0] + bA2), v5 = sspf(acc[mt][1][1] + bA3);
            bfsplit(v4, v5, hi, lo);
            *(uint32_t*)(sraw + S_AH + er * 272 + (ch0 + 8) * 2) = hi;
            *(uint32_t*)(sraw + S_AL + er * 272 + (ch0 + 8) * 2) = lo;
            float v6 = sspf(acc[mt][1][2] + bA2), v7 = sspf(acc[mt][1][3] + bA3);
            bfsplit(v6, v7, hi, lo);
            *(uint32_t*)(sraw + S_AH + (er + 8) * 272 + (ch0 + 8) * 2) = hi;
            *(uint32_t*)(sraw + S_AL + (er + 8) * 272 + (ch0 + 8) * 2) = lo;
        }
    }
    __syncthreads();

    // layer 2
    #pragma unroll
    for (int mt = 0; mt < 8; mt++)
        #pragma unroll
        for (int nt = 0; nt < 2; nt++)
            #pragma unroll
            for (int i = 0; i < 4; i++) acc[mt][nt][i] = 0.f;
    {
        const uint32_t ab[3] = { sb + S_AH + aoff2, sb + S_AH + aoff2, sb + S_AL + aoff2 };
        const uint32_t bb[3] = { sb + S_W2H + boff2, sb + S_W2L + boff2, sb + S_W2H + boff2 };
        #pragma unroll 1
        for (int t = 0; t < 3; t++) {
            #pragma unroll 1
            for (int ks = 0; ks < 8; ks++) {
                uint32_t bf0[2], bf1[2];
                ldsm_x2(bf0, bb[t] + ks * 32);
                ldsm_x2(bf1, bb[t] + 8 * 272 + ks * 32);
                #pragma unroll
                for (int mt = 0; mt < 8; mt++) {
                    uint32_t af[4];
                    ldsm_x4(af, ab[t] + mt * (16 * 272) + ks * 32);
                    mma_bf16(acc[mt][0], af, bf0);
                    mma_bf16(acc[mt][1], af, bf1);
                }
            }
        }
    }

    // epilogue 2: fp16 table
    {
        __half2* tbl = (__half2*)g_tableh[kblk];
        const int ch0 = wid * 16 + (lan & 3) * 2;
        const int cp  = ch0 >> 1;
        const float bB0 = b2g[ch0],     bB1 = b2g[ch0 + 1];
        const float bB2 = b2g[ch0 + 8], bB3 = b2g[ch0 + 9];
        #pragma unroll
        for (int mt = 0; mt < 8; mt++) {
            int r0 = e0 + mt * 16 + (lan >> 2);
            int r1 = r0 + 8;
            tbl[r0 * 64 + cp]     = __floats2half2_rn(acc[mt][0][0] + bB0, acc[mt][0][1] + bB1);
            tbl[r1 * 64 + cp]     = __floats2half2_rn(acc[mt][0][2] + bB0, acc[mt][0][3] + bB1);
            tbl[r0 * 64 + cp + 4] = __floats2half2_rn(acc[mt][1][0] + bB2, acc[mt][1][1] + bB3);
            tbl[r1 * 64 + cp + 4] = __floats2half2_rn(acc[mt][1][2] + bB2, acc[mt][1][3] + bB3);
        }
    }
}

// ---------------- message + aggregate: CSR gather, fp16 table lerp ----------
__global__ void __launch_bounds__(256)
k_msg(int kblk) {
    const int wid = threadIdx.x >> 5;
    const int lan = threadIdx.x & 31;
    const int n = blockIdx.x * 8 + wid;
    if (n >= NODES) return;
    const int s = g_ptr[n], e = g_ptr[n + 1];
    const uint2* __restrict__ T = (const uint2*)g_tableh[kblk];
    const uint2* __restrict__ X = (const uint2*)g_xh;
    float4 acc = make_float4(0.f, 0.f, 0.f, 0.f);
    #pragma unroll 2
    for (int j = s; j < e; j++) {
        const int4 m = __ldg(&g_meta[j]);
        const float w0 = __int_as_float(m.z);
        const float w1 = __int_as_float(m.w);
        const uint2 xr = X[m.x * 32 + lan];
        const uint2 t0 = T[m.y * 32 + lan];
        const uint2 t1 = T[m.y * 32 + 32 + lan];
        float2 xa = __half22float2(*(const __half2*)&xr.x);
        float2 xb = __half22float2(*(const __half2*)&xr.y);
        float2 a0 = __half22float2(*(const __half2*)&t0.x);
        float2 a1 = __half22float2(*(const __half2*)&t0.y);
        float2 b0 = __half22float2(*(const __half2*)&t1.x);
        float2 b1 = __half22float2(*(const __half2*)&t1.y);
        acc.x += xa.x * (a0.x * w0 + b0.x * w1);
        acc.y += xa.y * (a0.y * w0 + b0.y * w1);
        acc.z += xb.x * (a1.x * w0 + b1.x * w1);
        acc.w += xb.y * (a1.y * w0 + b1.y * w1);
    }
    ((float4*)g_agg)[n * 32 + lan] = acc;
}

// ------ fused node GEMMs, cp.async double-buffered, SINGLE WAVE (139 CTAs) ---
// Phases: A: mid = ssp(agg@W2+b2); B: h += mid@Wl+bl;
//   DO_C:   C: xh = h_new @ Wc (fp16)
//   DO_OUT: D: out = ssp(h_new@ow1+ob1)@ow2 + ob2
#define GF_SMEM ((16384 * 2 + NPC * HIDC) * 4)   // 167936 B

template <bool DO_C, bool DO_OUT>
__global__ void __launch_bounds__(512, 1)
k_gfused(const float* __restrict__ W2, const float* __restrict__ b2v,
         const float* __restrict__ Wl, const float* __restrict__ blv,
         const float* __restrict__ Wc,
         const float* __restrict__ ow1, const float* __restrict__ ob1,
         const float* __restrict__ ow2, const float* __restrict__ ob2,
         float* __restrict__ out) {
    extern __shared__ __align__(16) unsigned char sraw[];
    float* W0   = (float*)sraw;                     // 64 KB
    float* W1   = W0 + 16384;                       // 64 KB
    float* data = W1 + 16384;                       // 36 KB
    const uint32_t sW0 = smem_u32(W0);
    const uint32_t sW1 = smem_u32(W1);
    const uint32_t sD  = smem_u32(data);

    const int tid = threadIdx.x;
    const int f2  = tid & 63;
    const int grp = tid >> 6;       // 0..7
    const int n0  = blockIdx.x * NPC;
    const int nb  = grp * GNP;

    // group 0: W2 + agg tile
    {
        uint64_t gw = __cvta_generic_to_global(W2);
        #pragma unroll
        for (int i = tid; i < 4096; i += 512) CP16(sW0 + i * 16, gw + i * 16);
        uint64_t ga = __cvta_generic_to_global(g_agg);
        for (int i = tid; i < NPC * 32; i += 512) {
            int n = n0 + (i >> 5);
            int nc = (n < NODES) ? n : NODES - 1;
            CP16(sD + i * 16, ga + (uint64_t)(nc * 32 + (i & 31)) * 16);
        }
    }
    CP_COMMIT();
    // group 1: Wl
    {
        uint64_t gw = __cvta_generic_to_global(Wl);
        #pragma unroll
        for (int i = tid; i < 4096; i += 512) CP16(sW1 + i * 16, gw + i * 16);
    }
    CP_COMMIT();

    const float b2a = b2v[f2],      b2b = b2v[f2 + 64];
    const float bla = blv[f2],      blb = blv[f2 + 64];

    CP_WAIT(1);
    __syncthreads();

    // ---- phase A: mid = ssp(agg @ W2 + b2) ----
    float mida[GNP], midb[GNP];
    {
        ull acc0[GNP], acc1[GNP];
        #pragma unroll
        for (int e = 0; e < GNP; e++) { acc0[e] = pack2(b2a, 0.f); acc1[e] = pack2(b2b, 0.f); }
        #pragma unroll 1
        for (int c = 0; c < HIDC; c += 4) {
            ull wa01 = pack2(W0[c * HIDC + f2],       W0[(c + 1) * HIDC + f2]);
            ull wa23 = pack2(W0[(c + 2) * HIDC + f2], W0[(c + 3) * HIDC + f2]);
            ull wb01 = pack2(W0[c * HIDC + f2 + 64],       W0[(c + 1) * HIDC + f2 + 64]);
            ull wb23 = pack2(W0[(c + 2) * HIDC + f2 + 64], W0[(c + 3) * HIDC + f2 + 64]);
            #pragma unroll
            for (int e = 0; e < GNP; e++) {
                ulonglong2 hv = *(const ulonglong2*)&data[(nb + e) * HIDC + c];
                acc0[e] = fma2(hv.x, wa01, acc0[e]);
                acc0[e] = fma2(hv.y, wa23, acc0[e]);
                acc1[e] = fma2(hv.x, wb01, acc1[e]);
                acc1[e] = fma2(hv.y, wb23, acc1[e]);
            }
        }
        #pragma unroll
        for (int e = 0; e < GNP; e++) {
            float a, b;
            unpack2(acc0[e], a, b); mida[e] = sspf(a + b);
            unpack2(acc1[e], a, b); midb[e] = sspf(a + b);
        }
    }
    __syncthreads();

    // data = mid ; prefetch next matrix -> W0
    #pragma unroll
    for (int e = 0; e < GNP; e++) {
        data[(nb + e) * HIDC + f2]      = mida[e];
        data[(nb + e) * HIDC + f2 + 64] = midb[e];
    }
    if (DO_C) {
        uint64_t gw = __cvta_generic_to_global(Wc);
        #pragma unroll
        for (int i = tid; i < 4096; i += 512) CP16(sW0 + i * 16, gw + i * 16);
        CP_COMMIT();
        CP_WAIT(1);
    } else if (DO_OUT) {
        uint64_t gw = __cvta_generic_to_global(ow1);   // 128x64 = 2048 int4
        #pragma unroll
        for (int i = tid; i < 2048; i += 512) CP16(sW0 + i * 16, gw + i * 16);
        CP_COMMIT();
        CP_WAIT(1);
    } else {
        CP_WAIT(0);
    }
    __syncthreads();

    // ---- phase B: h_new = h + mid @ Wl + bl ----
    float hna[GNP], hnb[GNP];
    {
        ull acc0[GNP], acc1[GNP];
        #pragma unroll
        for (int e = 0; e < GNP; e++) { acc0[e] = pack2(bla, 0.f); acc1[e] = pack2(blb, 0.f); }
        #pragma unroll 1
        for (int c = 0; c < HIDC; c += 4) {
            ull wa01 = pack2(W1[c * HIDC + f2],       W1[(c + 1) * HIDC + f2]);
            ull wa23 = pack2(W1[(c + 2) * HIDC + f2], W1[(c + 3) * HIDC + f2]);
            ull wb01 = pack2(W1[c * HIDC + f2 + 64],       W1[(c + 1) * HIDC + f2 + 64]);
            ull wb23 = pack2(W1[(c + 2) * HIDC + f2 + 64], W1[(c + 3) * HIDC + f2 + 64]);
            #pragma unroll
            for (int e = 0; e < GNP; e++) {
                ulonglong2 hv = *(const ulonglong2*)&data[(nb + e) * HIDC + c];
                acc0[e] = fma2(hv.x, wa01, acc0[e]);
                acc0[e] = fma2(hv.y, wa23, acc0[e]);
                acc1[e] = fma2(hv.x, wb01, acc1[e]);
                acc1[e] = fma2(hv.y, wb23, acc1[e]);
            }
        }
        #pragma unroll
        for (int e = 0; e < GNP; e++) {
            int n = n0 + nb + e;
            float a, b;
            unpack2(acc0[e], a, b);
            float h0 = (n < NODES) ? g_h[n * HIDC + f2] : 0.f;
            hna[e] = h0 + a + b;
            unpack2(acc1[e], a, b);
            float h1 = (n < NODES) ? g_h[n * HIDC + f2 + 64] : 0.f;
            hnb[e] = h1 + a + b;
            if (n < NODES) {
                g_h[n * HIDC + f2]      = hna[e];
                g_h[n * HIDC + f2 + 64] = hnb[e];
            }
        }
    }
    if (!DO_C && !DO_OUT) return;

    __syncthreads();    // phase B reads of data done

    // data = h_new
    #pragma unroll
    for (int e = 0; e < GNP; e++) {
        data[(nb + e) * HIDC + f2]      = hna[e];
        data[(nb + e) * HIDC + f2 + 64] = hnb[e];
    }
    CP_WAIT(0);
    __syncthreads();

    if (DO_C) {
        // ---- phase C: xh = h_new @ Wc (fp16) ----
        ull acc0[GNP], acc1[GNP];
        #pragma unroll
        for (int e = 0; e < GNP; e++) { acc0[e] = pack2(0.f, 0.f); acc1[e] = pack2(0.f, 0.f); }
        #pragma unroll 1
        for (int c = 0; c < HIDC; c += 4) {
            ull wa01 = pack2(W0[c * HIDC + f2],       W0[(c + 1) * HIDC + f2]);
            ull wa23 = pack2(W0[(c + 2) * HIDC + f2], W0[(c + 3) * HIDC + f2]);
            ull wb01 = pack2(W0[c * HIDC + f2 + 64],       W0[(c + 1) * HIDC + f2 + 64]);
            ull wb23 = pack2(W0[(c + 2) * HIDC + f2 + 64], W0[(c + 3) * HIDC + f2 + 64]);
            #pragma unroll
            for (int e = 0; e < GNP; e++) {
                ulonglong2 hv = *(const ulonglong2*)&data[(nb + e) * HIDC + c];
                acc0[e] = fma2(hv.x, wa01, acc0[e]);
                acc0[e] = fma2(hv.y, wa23, acc0[e]);
                acc1[e] = fma2(hv.x, wb01, acc1[e]);
                acc1[e] = fma2(hv.y, wb23, acc1[e]);
            }
        }
        #pragma unroll
        for (int e = 0; e < GNP; e++) {
            int n = n0 + nb + e;
            if (n < NODES) {
                float a, b;
                unpack2(acc0[e], a, b);
                g_xh[n * HIDC + f2]      = __float2half(a + b);
                unpack2(acc1[e], a, b);
                g_xh[n * HIDC + f2 + 64] = __float2half(a + b);
            }
        }
    }

    if (DO_OUT) {
        // ---- phase D: out = ssp(h_new @ ow1 + ob1) @ ow2 + ob2 ----
        // thread f2 owns output-hidden channel f2 (64 channels); ow1 is [128][64]
        const float ob1v = ob1[f2];
        const float ow2v = ow2[f2];
        ull accO[GNP];
        #pragma unroll
        for (int e = 0; e < GNP; e++) accO[e] = pack2(ob1v, 0.f);
        #pragma unroll 1
        for (int c = 0; c < HIDC; c += 4) {
            ull w01 = pack2(W0[c * 64 + f2],       W0[(c + 1) * 64 + f2]);
            ull w23 = pack2(W0[(c + 2) * 64 + f2], W0[(c + 3) * 64 + f2]);
            #pragma unroll
            for (int e = 0; e < GNP; e++) {
                ulonglong2 hv = *(const ulonglong2*)&data[(nb + e) * HIDC + c];
                accO[e] = fma2(hv.x, w01, accO[e]);
                accO[e] = fma2(hv.y, w23, accO[e]);
            }
        }
        float s[GNP];
        #pragma unroll
        for (int e = 0; e < GNP; e++) {
            float a, b; unpack2(accO[e], a, b);
            s[e] = sspf(a + b) * ow2v;
        }
        // warp reduce (lanes carry consecutive f2 within each half)
        #pragma unroll
        for (int off = 16; off > 0; off >>= 1)
            #pragma unroll
            for (int e = 0; e < GNP; e++)
                s[e] += __shfl_down_sync(0xffffffffu, s[e], off);
        __syncthreads();   // all reads of data (phase D loop) complete
        float* part = data;   // reuse: [16 warps][GNP]
        const int wid = tid >> 5;   // = grp*2 + (f2>=32)
        if ((tid & 31) == 0) {
            #pragma unroll
            for (int e = 0; e < GNP; e++) part[wid * GNP + e] = s[e];
        }
        __syncthreads();
        if (tid < NPC) {
            int g = tid / GNP, e = tid % GNP;
            int n = n0 + tid;
            if (n < NODES)
                out[n] = part[(g * 2) * GNP + e] + part[(g * 2 + 1) * GNP + e] + ob2[0];
        }
    }
}

// ---------------- launcher ---------------------------------------------------
extern "C" void kernel_launch(void* const* d_in, const int* in_sizes, int n_in,
                              void* d_out, int out_size) {
    const int*   z    = (const int*)d_in[0];
    const float* pos  = (const float*)d_in[1];
    const int*   ei   = (const int*)d_in[2];
    const float* emb  = (const float*)d_in[3];
    const float* mw1  = (const float*)d_in[4];
    const float* mb1  = (const float*)d_in[5];
    const float* mw2  = (const float*)d_in[6];
    const float* mb2  = (const float*)d_in[7];
    const float* cl1  = (const float*)d_in[8];
    const float* cl2  = (const float*)d_in[9];
    const float* cl2b = (const float*)d_in[10];
    const float* lw   = (const float*)d_in[11];
    const float* lb   = (const float*)d_in[12];
    const float* ow1  = (const float*)d_in[13];
    const float* ob1  = (const float*)d_in[14];
    const float* ow2  = (const float*)d_in[15];
    const float* ob2  = (const float*)d_in[16];
    float* out = (float*)d_out;

    const int* row = ei;
    const int* col = ei + EDGES;

    cudaFuncSetAttribute(k_tbuild, cudaFuncAttributeMaxDynamicSharedMemorySize, FILT_SMEM);
    cudaFuncSetAttribute((const void*)k_gfused<true, false>,
                         cudaFuncAttributeMaxDynamicSharedMemorySize, GF_SMEM);
    cudaFuncSetAttribute((const void*)k_gfused<false, true>,
                         cudaFuncAttributeMaxDynamicSharedMemorySize, GF_SMEM);

    // one-time (per launch) prep
    k_wprep<<<NBLK + 1, 256>>>(mw1, mw2, emb, cl1);          // weights + embx + zero cnt
    k_embed<<<(NODES * HIDC + 255) / 256, 256>>>(z, emb, col); // h, x0 gather, CSR count
    k_scan<<<1, 1024>>>();
    k_fill<<<(EDGES + 255) / 256, 256>>>(pos, row, col);
    {
        dim3 tg(TROWS / 128, NBLK);
        k_tbuild<<<tg, 256, FILT_SMEM>>>(mb1, mb2);
    }

    const int gfgrid = (NODES + NPC - 1) / NPC;          // 139 <= 148: one wave
    const int mgrid  = (NODES + 7) / 8;

    for (int k = 0; k < NBLK; k++) {
        k_msg<<<mgrid, 256>>>(k);
        if (k < NBLK - 1) {
            k_gfused<true, false><<<gfgrid, 512, GF_SMEM>>>(
                cl2 + k * HIDC * HIDC, cl2b + k * HIDC,
                lw  + k * HIDC * HIDC, lb   + k * HIDC,
                cl1 + (k + 1) * HIDC * HIDC,
                nullptr, nullptr, nullptr, nullptr, nullptr);
        } else {
            k_gfused<false, true><<<gfgrid, 512, GF_SMEM>>>(
                cl2 + k * HIDC * HIDC, cl2b + k * HIDC,
                lw  + k * HIDC * HIDC, lb   + k * HIDC,
                nullptr, ow1, ob1, ow2, ob2, out);
        }
    }
}

// round 16
// speedup vs baseline: 1.3757x; 1.3757x over previous
#include <cuda_runtime.h>
#include <cuda_fp16.h>
#include <cuda_bf16.h>
#include <cstdint>

#define NODES   10000
#define EDGES   320000
#define HIDC    128
#define NGAUSS  50
#define NBLK    6

#define NPC     72     // nodes per CTA in fused GEMM kernel (512 thr, 8 grp x 9)
#define GNP     9      // nodes per thread-group

#define GDELTA  (10.0f / 49.0f)
#define GCOEFF  (-0.5f / (GDELTA * GDELTA))

#define TROWS   3072                     // filter table rows
#define DMAX    8.66025404f              // max possible d (box 5^3)
#define TSCALE  ((TROWS - 1) / DMAX)
#define DSTEP   (DMAX / (TROWS - 1))

// ---------------- scratch (device globals; no runtime allocation) ----------
__device__ float  g_h[NODES * HIDC];
__device__ __align__(16) __half g_xh[NODES * HIDC];   // x in fp16 (message path)
__device__ float  g_agg[NODES * HIDC];
__device__ float  g_embx[100 * HIDC];                 // emb @ cl1[0]

// CSR by target node + per-edge interp metadata
__device__ int  g_cnt[NODES];
__device__ int  g_rank[EDGES];
__device__ int  g_ptr[NODES + 1];
__device__ __align__(16) int4 g_meta[EDGES];   // {row, tbase, w0_bits, w1_bits}

// filter tables in fp16: W_k(d) on TROWS points, [TROWS][128] per block
__device__ __align__(16) __half g_tableh[NBLK][TROWS * HIDC];

// pre-split bf16 hi/lo weight images, padded row-major [ch][Kpad]
__device__ __align__(16) uint32_t g_w1h[NBLK][4608];
__device__ __align__(16) uint32_t g_w1l[NBLK][4608];
__device__ __align__(16) uint32_t g_w2h[NBLK][8704];
__device__ __align__(16) uint32_t g_w2l[NBLK][8704];

// ---------------- helpers ---------------------------------------------------
using ull = unsigned long long;

__device__ __forceinline__ uint32_t smem_u32(const void* p) {
    uint32_t a;
    asm("{ .reg .u64 t; cvta.to.shared.u64 t, %1; cvt.u32.u64 %0, t; }" : "=r"(a) : "l"(p));
    return a;
}
#define CP16(s, g) asm volatile("cp.async.cg.shared.global [%0], [%1], 16;" :: "r"(s), "l"(g))
#define CP_COMMIT() asm volatile("cp.async.commit_group;" ::: "memory")
#define CP_WAIT(n)  asm volatile("cp.async.wait_group %0;" :: "n"(n) : "memory")

__device__ __forceinline__ void ldsm_x4(uint32_t* r, uint32_t addr) {
    asm volatile("ldmatrix.sync.aligned.m8n8.x4.shared.b16 {%0,%1,%2,%3}, [%4];"
                 : "=r"(r[0]), "=r"(r[1]), "=r"(r[2]), "=r"(r[3]) : "r"(addr));
}
__device__ __forceinline__ void ldsm_x2(uint32_t* r, uint32_t addr) {
    asm volatile("ldmatrix.sync.aligned.m8n8.x2.shared.b16 {%0,%1}, [%2];"
                 : "=r"(r[0]), "=r"(r[1]) : "r"(addr));
}
__device__ __forceinline__ void mma_bf16(float* c, const uint32_t* a, const uint32_t* b) {
    asm volatile("mma.sync.aligned.m16n8k16.row.col.f32.bf16.bf16.f32 "
                 "{%0,%1,%2,%3}, {%4,%5,%6,%7}, {%8,%9}, {%0,%1,%2,%3};"
                 : "+f"(c[0]), "+f"(c[1]), "+f"(c[2]), "+f"(c[3])
                 : "r"(a[0]), "r"(a[1]), "r"(a[2]), "r"(a[3]), "r"(b[0]), "r"(b[1]));
}
__device__ __forceinline__ uint32_t bfpair(float f0, float f1) {
    uint32_t r;
    asm("cvt.rn.bf16x2.f32 %0, %1, %2;" : "=r"(r) : "f"(f1), "f"(f0));
    return r;
}
__device__ __forceinline__ void bfsplit(float f0, float f1, uint32_t& hi, uint32_t& lo) {
    hi = bfpair(f0, f1);
    float h0 = __uint_as_float(hi << 16);
    float h1 = __uint_as_float(hi & 0xFFFF0000u);
    lo = bfpair(f0 - h0, f1 - h1);
}
__device__ __forceinline__ float sspf(float v) {
    float t, u;
    asm("ex2.approx.f32 %0, %1;" : "=f"(t) : "f"(v * 1.4426950408889634f));
    asm("lg2.approx.f32 %0, %1;" : "=f"(u) : "f"(fmaf(0.5f, t, 0.5f)));
    return 0.6931471805599453f * u;
}
__device__ __forceinline__ ull pack2(float a, float b) {
    ull r; asm("mov.b64 %0, {%1, %2};" : "=l"(r) : "f"(a), "f"(b)); return r;
}
__device__ __forceinline__ void unpack2(ull v, float& a, float& b) {
    asm("mov.b64 {%0, %1}, %2;" : "=f"(a), "=f"(b) : "l"(v));
}
__device__ __forceinline__ ull fma2(ull a, ull b, ull c) {
    ull r; asm("fma.rn.f32x2 %0, %1, %2, %3;" : "=l"(r) : "l"(a), "l"(b), "l"(c));
    return r;
}

// ---------------- weight prep + zero CSR counters + parallel embx -----------
// grid = NBLK + 50. Blocks 0..5: filter weights. Blocks 6..55: embx (2 rows each).
__global__ void k_wprep(const float* __restrict__ mw1, const float* __restrict__ mw2,
                        const float* __restrict__ emb, const float* __restrict__ cl1) {
    const int k = blockIdx.x;
    for (int i = blockIdx.x * blockDim.x + threadIdx.x; i < NODES; i += gridDim.x * blockDim.x)
        g_cnt[i] = 0;
    if (k >= NBLK) {
        // embx rows 2*(k-NBLK) .. +1 (one output per thread, coalesced over c)
        int r = 2 * (k - NBLK) + (threadIdx.x >> 7);
        int c = threadIdx.x & 127;
        float s = 0.f;
        #pragma unroll 8
        for (int kk = 0; kk < HIDC; kk++) s += emb[r * HIDC + kk] * cl1[kk * HIDC + c];
        g_embx[r * HIDC + c] = s;
        return;
    }
    const float* w1 = mw1 + k * NGAUSS * HIDC;
    const float* w2 = mw2 + k * HIDC * HIDC;
    for (int i = threadIdx.x; i < 4608; i += blockDim.x) {
        int c = i / 36, kk = (i % 36) * 2;
        float v0 = (kk     < NGAUSS) ? w1[kk * HIDC + c]       : 0.f;
        float v1 = (kk + 1 < NGAUSS) ? w1[(kk + 1) * HIDC + c] : 0.f;
        uint32_t hi, lo; bfsplit(v0, v1, hi, lo);
        g_w1h[k][i] = hi; g_w1l[k][i] = lo;
    }
    for (int i = threadIdx.x; i < 8704; i += blockDim.x) {
        int c = i / 68, kk = (i % 68) * 2;
        float v0 = (kk     < HIDC) ? w2[kk * HIDC + c]       : 0.f;
        float v1 = (kk + 1 < HIDC) ? w2[(kk + 1) * HIDC + c] : 0.f;
        uint32_t hi, lo; bfsplit(v0, v1, hi, lo);
        g_w2h[k][i] = hi; g_w2l[k][i] = lo;
    }
}

// ---------------- embedding gather + CSR count + x0 gather ------------------
__global__ void k_embed(const int* __restrict__ z, const float* __restrict__ emb,
                        const int* __restrict__ col) {
    int i = blockIdx.x * blockDim.x + threadIdx.x;
    if (i < EDGES) g_rank[i] = atomicAdd(&g_cnt[col[i]], 1);
    if (i >= NODES * HIDC) return;
    int zi = z[i >> 7] * HIDC + (i & 127);
    g_h[i]  = emb[zi];
    g_xh[i] = __float2half(g_embx[zi]);   // x0 = h @ cl1[0] via precomputed embx
}

// ---------------- CSR scan ----------------------------------------------------
__global__ void k_scan() {   // single block, 1024 threads, chunk=10
    __shared__ int s[1024];
    const int t = threadIdx.x;
    const int base = t * 10;
    int local[10];
    int sum = 0;
    #pragma unroll
    for (int i = 0; i < 10; i++) {
        int idx = base + i;
        local[i] = (idx < NODES) ? g_cnt[idx] : 0;
        sum += local[i];
    }
    s[t] = sum;
    __syncthreads();
    for (int off = 1; off < 1024; off <<= 1) {
        int v = (t >= off) ? s[t - off] : 0;
        __syncthreads();
        s[t] += v;
        __syncthreads();
    }
    int run = (t > 0) ? s[t - 1] : 0;
    #pragma unroll
    for (int i = 0; i < 10; i++) {
        int idx = base + i;
        if (idx < NODES) { g_ptr[idx] = run; run += local[i]; }
    }
    if (t == 1023) g_ptr[NODES] = s[1023];
}
__global__ void k_fill(const float* __restrict__ pos,
                       const int* __restrict__ row, const int* __restrict__ col) {
    int e = blockIdx.x * blockDim.x + threadIdx.x;
    if (e >= EDGES) return;
    int r = row[e], c = col[e];
    float dx = pos[r * 3 + 0] - pos[c * 3 + 0];
    float dy = pos[r * 3 + 1] - pos[c * 3 + 1];
    float dz = pos[r * 3 + 2] - pos[c * 3 + 2];
    float d = sqrtf(dx * dx + dy * dy + dz * dz);
    float C = 0.5f * (cosf(d * (3.14159265358979323846f / 10.0f)) + 1.0f);
    int pos_ = g_ptr[c] + g_rank[e];
    float fidx = d * TSCALE;
    int tb = (int)fidx;
    if (tb > TROWS - 2) tb = TROWS - 2;
    float fr = fidx - (float)tb;
    int4 m;
    m.x = r;
    m.y = tb;
    m.z = __float_as_int((1.0f - fr) * C);
    m.w = __float_as_int(fr * C);
    g_meta[pos_] = m;
}

// ---------------- table build: MMA filter MLP on TROWS d-samples -------------
#define S_W1H 0
#define S_W1L 18432
#define S_W2H 36864
#define S_W2L 71680
#define S_AH  106496
#define S_AL  141312
#define FILT_SMEM 176128

__global__ void __launch_bounds__(256, 1)
k_tbuild(const float* __restrict__ mb1, const float* __restrict__ mb2) {
    extern __shared__ __align__(16) unsigned char sraw[];
    const uint32_t sb = smem_u32(sraw);
    const int tid  = threadIdx.x;
    const int wid  = tid >> 5;
    const int lan  = tid & 31;
    const int kblk = blockIdx.y;
    const int e0   = blockIdx.x * 128;
    const float* b1g = mb1 + kblk * HIDC;
    const float* b2g = mb2 + kblk * HIDC;

    {
        const int4* s1h = (const int4*)g_w1h[kblk];
        const int4* s1l = (const int4*)g_w1l[kblk];
        const int4* s2h = (const int4*)g_w2h[kblk];
        const int4* s2l = (const int4*)g_w2l[kblk];
        int4* d1h = (int4*)(sraw + S_W1H);
        int4* d1l = (int4*)(sraw + S_W1L);
        int4* d2h = (int4*)(sraw + S_W2H);
        int4* d2l = (int4*)(sraw + S_W2L);
        #pragma unroll 2
        for (int i = tid; i < 1152; i += 256) { d1h[i] = s1h[i]; d1l[i] = s1l[i]; }
        #pragma unroll 4
        for (int i = tid; i < 2176; i += 256) { d2h[i] = s2h[i]; d2l[i] = s2l[i]; }
    }

    for (int i = tid; i < 128 * 36; i += 256) {
        int e = i / 36, kk = (i % 36) * 2;
        float d = (float)(e0 + e) * DSTEP;
        float v0 = 0.f, v1 = 0.f;
        if (kk < NGAUSS)     { float dd = d - (float)kk * GDELTA;       v0 = __expf(GCOEFF * dd * dd); }
        if (kk + 1 < NGAUSS) { float dd = d - (float)(kk + 1) * GDELTA; v1 = __expf(GCOEFF * dd * dd); }
        uint32_t hi, lo; bfsplit(v0, v1, hi, lo);
        *(uint32_t*)(sraw + S_AH + e * 144 + kk * 2) = hi;
        *(uint32_t*)(sraw + S_AL + e * 144 + kk * 2) = lo;
    }
    __syncthreads();

    const uint32_t aoff1 = (lan & 15) * 144 + (lan >> 4) * 16;
    const uint32_t boff1 = (wid * 16 + (lan & 7)) * 144 + ((lan >> 3) & 1) * 16;
    const uint32_t aoff2 = (lan & 15) * 272 + (lan >> 4) * 16;
    const uint32_t boff2 = (wid * 16 + (lan & 7)) * 272 + ((lan >> 3) & 1) * 16;

    float acc[8][2][4];

    // layer 1
    #pragma unroll
    for (int mt = 0; mt < 8; mt++)
        #pragma unroll
        for (int nt = 0; nt < 2; nt++)
            #pragma unroll
            for (int i = 0; i < 4; i++) acc[mt][nt][i] = 0.f;
    {
        const uint32_t ab[3] = { sb + S_AH + aoff1, sb + S_AH + aoff1, sb + S_AL + aoff1 };
        const uint32_t bb[3] = { sb + S_W1H + boff1, sb + S_W1L + boff1, sb + S_W1H + boff1 };
        #pragma unroll 1
        for (int t = 0; t < 3; t++) {
            #pragma unroll 1
            for (int ks = 0; ks < 4; ks++) {
                uint32_t bf0[2], bf1[2];
                ldsm_x2(bf0, bb[t] + ks * 32);
                ldsm_x2(bf1, bb[t] + 8 * 144 + ks * 32);
                #pragma unroll
                for (int mt = 0; mt < 8; mt++) {
                    uint32_t af[4];
                    ldsm_x4(af, ab[t] + mt * (16 * 144) + ks * 32);
                    mma_bf16(acc[mt][0], af, bf0);
                    mma_bf16(acc[mt][1], af, bf1);
                }
            }
        }
    }
    __syncthreads();

    // epilogue 1
    {
        const int ch0 = wid * 16 + (lan & 3) * 2;
        const float bA0 = b1g[ch0],     bA1 = b1g[ch0 + 1];
        const float bA2 = b1g[ch0 + 8], bA3 = b1g[ch0 + 9];
        #pragma unroll
        for (int mt = 0; mt < 8; mt++) {
            int er = mt * 16 + (lan >> 2);
            uint32_t hi, lo;
            float v0 = sspf(acc[mt][0][0] + bA0), v1 = sspf(acc[mt][0][1] + bA1);
            bfsplit(v0, v1, hi, lo);
            *(uint32_t*)(sraw + S_AH + er * 272 + ch0 * 2) = hi;
            *(uint32_t*)(sraw + S_AL + er * 272 + ch0 * 2) = lo;
            float v2 = sspf(acc[mt][0][2] + bA0), v3 = sspf(acc[mt][0][3] + bA1);
            bfsplit(v2, v3, hi, lo);
            *(uint32_t*)(sraw + S_AH + (er + 8) * 272 + ch0 * 2) = hi;
            *(uint32_t*)(sraw + S_AL + (er + 8) * 272 + ch0 * 2) = lo;
            float v4 = sspf(acc[mt][1][0] + bA2), v5 = sspf(acc[mt][1][1] + bA3);
            bfsplit(v4, v5, hi, lo);
            *(uint32_t*)(sraw + S_AH + er * 272 + (ch0 + 8) * 2) = hi;
            *(uint32_t*)(sraw + S_AL + er * 272 + (ch0 + 8) * 2) = lo;
            float v6 = sspf(acc[mt][1][2] + bA2), v7 = sspf(acc[mt][1][3] + bA3);
            bfsplit(v6, v7, hi, lo);
            *(uint32_t*)(sraw + S_AH + (er + 8) * 272 + (ch0 + 8) * 2) = hi;
            *(uint32_t*)(sraw + S_AL + (er + 8) * 272 + (ch0 + 8) * 2) = lo;
        }
    }
    __syncthreads();

    // layer 2
    #pragma unroll
    for (int mt = 0; mt < 8; mt++)
        #pragma unroll
        for (int nt = 0; nt < 2; nt++)
            #pragma unroll
            for (int i = 0; i < 4; i++) acc[mt][nt][i] = 0.f;
    {
        const uint32_t ab[3] = { sb + S_AH + aoff2, sb + S_AH + aoff2, sb + S_AL + aoff2 };
        const uint32_t bb[3] = { sb + S_W2H + boff2, sb + S_W2L + boff2, sb + S_W2H + boff2 };
        #pragma unroll 1
        for (int t = 0; t < 3; t++) {
            #pragma unroll 1
            for (int ks = 0; ks < 8; ks++) {
                uint32_t bf0[2], bf1[2];
                ldsm_x2(bf0, bb[t] + ks * 32);
                ldsm_x2(bf1, bb[t] + 8 * 272 + ks * 32);
                #pragma unroll
                for (int mt = 0; mt < 8; mt++) {
                    uint32_t af[4];
                    ldsm_x4(af, ab[t] + mt * (16 * 272) + ks * 32);
                    mma_bf16(acc[mt][0], af, bf0);
                    mma_bf16(acc[mt][1], af, bf1);
                }
            }
        }
    }

    // epilogue 2: fp16 table
    {
        __half2* tbl = (__half2*)g_tableh[kblk];
        const int ch0 = wid * 16 + (lan & 3) * 2;
        const int cp  = ch0 >> 1;
        const float bB0 = b2g[ch0],     bB1 = b2g[ch0 + 1];
        const float bB2 = b2g[ch0 + 8], bB3 = b2g[ch0 + 9];
        #pragma unroll
        for (int mt = 0; mt < 8; mt++) {
            int r0 = e0 + mt * 16 + (lan >> 2);
            int r1 = r0 + 8;
            tbl[r0 * 64 + cp]     = __floats2half2_rn(acc[mt][0][0] + bB0, acc[mt][0][1] + bB1);
            tbl[r1 * 64 + cp]     = __floats2half2_rn(acc[mt][0][2] + bB0, acc[mt][0][3] + bB1);
            tbl[r0 * 64 + cp + 4] = __floats2half2_rn(acc[mt][1][0] + bB2, acc[mt][1][1] + bB3);
            tbl[r1 * 64 + cp + 4] = __floats2half2_rn(acc[mt][1][2] + bB2, acc[mt][1][3] + bB3);
        }
    }
}

// ---------------- message + aggregate: CSR gather, fp16 table lerp ----------
__global__ void __launch_bounds__(256)
k_msg(int kblk) {
    const int wid = threadIdx.x >> 5;
    const int lan = threadIdx.x & 31;
    const int n = blockIdx.x * 8 + wid;
    if (n >= NODES) return;
    const int s = g_ptr[n], e = g_ptr[n + 1];
    const uint2* __restrict__ T = (const uint2*)g_tableh[kblk];
    const uint2* __restrict__ X = (const uint2*)g_xh;
    float4 acc = make_float4(0.f, 0.f, 0.f, 0.f);
    #pragma unroll 2
    for (int j = s; j < e; j++) {
        const int4 m = __ldg(&g_meta[j]);
        const float w0 = __int_as_float(m.z);
        const float w1 = __int_as_float(m.w);
        const uint2 xr = X[m.x * 32 + lan];
        const uint2 t0 = T[m.y * 32 + lan];
        const uint2 t1 = T[m.y * 32 + 32 + lan];
        float2 xa = __half22float2(*(const __half2*)&xr.x);
        float2 xb = __half22float2(*(const __half2*)&xr.y);
        float2 a0 = __half22float2(*(const __half2*)&t0.x);
        float2 a1 = __half22float2(*(const __half2*)&t0.y);
        float2 b0 = __half22float2(*(const __half2*)&t1.x);
        float2 b1 = __half22float2(*(const __half2*)&t1.y);
        acc.x += xa.x * (a0.x * w0 + b0.x * w1);
        acc.y += xa.y * (a0.y * w0 + b0.y * w1);
        acc.z += xb.x * (a1.x * w0 + b1.x * w1);
        acc.w += xb.y * (a1.y * w0 + b1.y * w1);
    }
    ((float4*)g_agg)[n * 32 + lan] = acc;
}

// ------ fused node GEMMs, cp.async double-buffered, SINGLE WAVE (139 CTAs) ---
// Phases: A: mid = ssp(agg@W2+b2); B: h += mid@Wl+bl;
//   DO_C:   C: xh = h_new @ Wc (fp16)
//   DO_OUT: D: out = ssp(h_new@ow1+ob1)@ow2 + ob2
#define GF_SMEM ((16384 * 2 + NPC * HIDC) * 4)   // 167936 B

template <bool DO_C, bool DO_OUT>
__global__ void __launch_bounds__(512, 1)
k_gfused(const float* __restrict__ W2, const float* __restrict__ b2v,
         const float* __restrict__ Wl, const float* __restrict__ blv,
         const float* __restrict__ Wc,
         const float* __restrict__ ow1, const float* __restrict__ ob1,
         const float* __restrict__ ow2, const float* __restrict__ ob2,
         float* __restrict__ out) {
    extern __shared__ __align__(16) unsigned char sraw[];
    float* W0   = (float*)sraw;                     // 64 KB
    float* W1   = W0 + 16384;                       // 64 KB
    float* data = W1 + 16384;                       // 36 KB
    const uint32_t sW0 = smem_u32(W0);
    const uint32_t sW1 = smem_u32(W1);
    const uint32_t sD  = smem_u32(data);

    const int tid = threadIdx.x;
    const int f2  = tid & 63;
    const int grp = tid >> 6;       // 0..7
    const int n0  = blockIdx.x * NPC;
    const int nb  = grp * GNP;

    // group 0: W2 + agg tile
    {
        uint64_t gw = __cvta_generic_to_global(W2);
        #pragma unroll
        for (int i = tid; i < 4096; i += 512) CP16(sW0 + i * 16, gw + i * 16);
        uint64_t ga = __cvta_generic_to_global(g_agg);
        for (int i = tid; i < NPC * 32; i += 512) {
            int n = n0 + (i >> 5);
            int nc = (n < NODES) ? n : NODES - 1;
            CP16(sD + i * 16, ga + (uint64_t)(nc * 32 + (i & 31)) * 16);
        }
    }
    CP_COMMIT();
    // group 1: Wl
    {
        uint64_t gw = __cvta_generic_to_global(Wl);
        #pragma unroll
        for (int i = tid; i < 4096; i += 512) CP16(sW1 + i * 16, gw + i * 16);
    }
    CP_COMMIT();

    const float b2a = b2v[f2],      b2b = b2v[f2 + 64];
    const float bla = blv[f2],      blb = blv[f2 + 64];

    CP_WAIT(1);
    __syncthreads();

    // ---- phase A: mid = ssp(agg @ W2 + b2) ----
    float mida[GNP], midb[GNP];
    {
        ull acc0[GNP], acc1[GNP];
        #pragma unroll
        for (int e = 0; e < GNP; e++) { acc0[e] = pack2(b2a, 0.f); acc1[e] = pack2(b2b, 0.f); }
        #pragma unroll 1
        for (int c = 0; c < HIDC; c += 4) {
            ull wa01 = pack2(W0[c * HIDC + f2],       W0[(c + 1) * HIDC + f2]);
            ull wa23 = pack2(W0[(c + 2) * HIDC + f2], W0[(c + 3) * HIDC + f2]);
            ull wb01 = pack2(W0[c * HIDC + f2 + 64],       W0[(c + 1) * HIDC + f2 + 64]);
            ull wb23 = pack2(W0[(c + 2) * HIDC + f2 + 64], W0[(c + 3) * HIDC + f2 + 64]);
            #pragma unroll
            for (int e = 0; e < GNP; e++) {
                ulonglong2 hv = *(const ulonglong2*)&data[(nb + e) * HIDC + c];
                acc0[e] = fma2(hv.x, wa01, acc0[e]);
                acc0[e] = fma2(hv.y, wa23, acc0[e]);
                acc1[e] = fma2(hv.x, wb01, acc1[e]);
                acc1[e] = fma2(hv.y, wb23, acc1[e]);
            }
        }
        #pragma unroll
        for (int e = 0; e < GNP; e++) {
            float a, b;
            unpack2(acc0[e], a, b); mida[e] = sspf(a + b);
            unpack2(acc1[e], a, b); midb[e] = sspf(a + b);
        }
    }
    __syncthreads();

    // data = mid ; prefetch next matrix -> W0
    #pragma unroll
    for (int e = 0; e < GNP; e++) {
        data[(nb + e) * HIDC + f2]      = mida[e];
        data[(nb + e) * HIDC + f2 + 64] = midb[e];
    }
    if (DO_C) {
        uint64_t gw = __cvta_generic_to_global(Wc);
        #pragma unroll
        for (int i = tid; i < 4096; i += 512) CP16(sW0 + i * 16, gw + i * 16);
        CP_COMMIT();
        CP_WAIT(1);
    } else if (DO_OUT) {
        uint64_t gw = __cvta_generic_to_global(ow1);   // 128x64 = 2048 int4
        #pragma unroll
        for (int i = tid; i < 2048; i += 512) CP16(sW0 + i * 16, gw + i * 16);
        CP_COMMIT();
        CP_WAIT(1);
    } else {
        CP_WAIT(0);
    }
    __syncthreads();

    // ---- phase B: h_new = h + mid @ Wl + bl ----
    float hna[GNP], hnb[GNP];
    {
        ull acc0[GNP], acc1[GNP];
        #pragma unroll
        for (int e = 0; e < GNP; e++) { acc0[e] = pack2(bla, 0.f); acc1[e] = pack2(blb, 0.f); }
        #pragma unroll 1
        for (int c = 0; c < HIDC; c += 4) {
            ull wa01 = pack2(W1[c * HIDC + f2],       W1[(c + 1) * HIDC + f2]);
            ull wa23 = pack2(W1[(c + 2) * HIDC + f2], W1[(c + 3) * HIDC + f2]);
            ull wb01 = pack2(W1[c * HIDC + f2 + 64],       W1[(c + 1) * HIDC + f2 + 64]);
            ull wb23 = pack2(W1[(c + 2) * HIDC + f2 + 64], W1[(c + 3) * HIDC + f2 + 64]);
            #pragma unroll
            for (int e = 0; e < GNP; e++) {
                ulonglong2 hv = *(const ulonglong2*)&data[(nb + e) * HIDC + c];
                acc0[e] = fma2(hv.x, wa01, acc0[e]);
                acc0[e] = fma2(hv.y, wa23, acc0[e]);
                acc1[e] = fma2(hv.x, wb01, acc1[e]);
                acc1[e] = fma2(hv.y, wb23, acc1[e]);
            }
        }
        #pragma unroll
        for (int e = 0; e < GNP; e++) {
            int n = n0 + nb + e;
            float a, b;
            unpack2(acc0[e], a, b);
            float h0 = (n < NODES) ? g_h[n * HIDC + f2] : 0.f;
            hna[e] = h0 + a + b;
            unpack2(acc1[e], a, b);
            float h1 = (n < NODES) ? g_h[n * HIDC + f2 + 64] : 0.f;
            hnb[e] = h1 + a + b;
            if (n < NODES) {
                g_h[n * HIDC + f2]      = hna[e];
                g_h[n * HIDC + f2 + 64] = hnb[e];
            }
        }
    }
    if (!DO_C && !DO_OUT) return;

    __syncthreads();    // phase B reads of data done

    // data = h_new
    #pragma unroll
    for (int e = 0; e < GNP; e++) {
        data[(nb + e) * HIDC + f2]      = hna[e];
        data[(nb + e) * HIDC + f2 + 64] = hnb[e];
    }
    CP_WAIT(0);
    __syncthreads();

    if (DO_C) {
        // ---- phase C: xh = h_new @ Wc (fp16) ----
        ull acc0[GNP], acc1[GNP];
        #pragma unroll
        for (int e = 0; e < GNP; e++) { acc0[e] = pack2(0.f, 0.f); acc1[e] = pack2(0.f, 0.f); }
        #pragma unroll 1
        for (int c = 0; c < HIDC; c += 4) {
            ull wa01 = pack2(W0[c * HIDC + f2],       W0[(c + 1) * HIDC + f2]);
            ull wa23 = pack2(W0[(c + 2) * HIDC + f2], W0[(c + 3) * HIDC + f2]);
            ull wb01 = pack2(W0[c * HIDC + f2 + 64],       W0[(c + 1) * HIDC + f2 + 64]);
            ull wb23 = pack2(W0[(c + 2) * HIDC + f2 + 64], W0[(c + 3) * HIDC + f2 + 64]);
            #pragma unroll
            for (int e = 0; e < GNP; e++) {
                ulonglong2 hv = *(const ulonglong2*)&data[(nb + e) * HIDC + c];
                acc0[e] = fma2(hv.x, wa01, acc0[e]);
                acc0[e] = fma2(hv.y, wa23, acc0[e]);
                acc1[e] = fma2(hv.x, wb01, acc1[e]);
                acc1[e] = fma2(hv.y, wb23, acc1[e]);
            }
        }
        #pragma unroll
        for (int e = 0; e < GNP; e++) {
            int n = n0 + nb + e;
            if (n < NODES) {
                float a, b;
                unpack2(acc0[e], a, b);
                g_xh[n * HIDC + f2]      = __float2half(a + b);
                unpack2(acc1[e], a, b);
                g_xh[n * HIDC + f2 + 64] = __float2half(a + b);
            }
        }
    }

    if (DO_OUT) {
        // ---- phase D: out = ssp(h_new @ ow1 + ob1) @ ow2 + ob2 ----
        const float ob1v = ob1[f2];
        const float ow2v = ow2[f2];
        ull accO[GNP];
        #pragma unroll
        for (int e = 0; e < GNP; e++) accO[e] = pack2(ob1v, 0.f);
        #pragma unroll 1
        for (int c = 0; c < HIDC; c += 4) {
            ull w01 = pack2(W0[c * 64 + f2],       W0[(c + 1) * 64 + f2]);
            ull w23 = pack2(W0[(c + 2) * 64 + f2], W0[(c + 3) * 64 + f2]);
            #pragma unroll
            for (int e = 0; e < GNP; e++) {
                ulonglong2 hv = *(const ulonglong2*)&data[(nb + e) * HIDC + c];
                accO[e] = fma2(hv.x, w01, accO[e]);
                accO[e] = fma2(hv.y, w23, accO[e]);
            }
        }
        float s[GNP];
        #pragma unroll
        for (int e = 0; e < GNP; e++) {
            float a, b; unpack2(accO[e], a, b);
            s[e] = sspf(a + b) * ow2v;
        }
        #pragma unroll
        for (int off = 16; off > 0; off >>= 1)
            #pragma unroll
            for (int e = 0; e < GNP; e++)
                s[e] += __shfl_down_sync(0xffffffffu, s[e], off);
        __syncthreads();
        float* part = data;   // reuse: [16 warps][GNP]
        const int wid = tid >> 5;
        if ((tid & 31) == 0) {
            #pragma unroll
            for (int e = 0; e < GNP; e++) part[wid * GNP + e] = s[e];
        }
        __syncthreads();
        if (tid < NPC) {
            int g = tid / GNP, e = tid % GNP;
            int n = n0 + tid;
            if (n < NODES)
                out[n] = part[(g * 2) * GNP + e] + part[(g * 2 + 1) * GNP + e] + ob2[0];
        }
    }
}

// ---------------- launcher ---------------------------------------------------
extern "C" void kernel_launch(void* const* d_in, const int* in_sizes, int n_in,
                              void* d_out, int out_size) {
    const int*   z    = (const int*)d_in[0];
    const float* pos  = (const float*)d_in[1];
    const int*   ei   = (const int*)d_in[2];
    const float* emb  = (const float*)d_in[3];
    const float* mw1  = (const float*)d_in[4];
    const float* mb1  = (const float*)d_in[5];
    const float* mw2  = (const float*)d_in[6];
    const float* mb2  = (const float*)d_in[7];
    const float* cl1  = (const float*)d_in[8];
    const float* cl2  = (const float*)d_in[9];
    const float* cl2b = (const float*)d_in[10];
    const float* lw   = (const float*)d_in[11];
    const float* lb   = (const float*)d_in[12];
    const float* ow1  = (const float*)d_in[13];
    const float* ob1  = (const float*)d_in[14];
    const float* ow2  = (const float*)d_in[15];
    const float* ob2  = (const float*)d_in[16];
    float* out = (float*)d_out;

    const int* row = ei;
    const int* col = ei + EDGES;

    cudaFuncSetAttribute(k_tbuild, cudaFuncAttributeMaxDynamicSharedMemorySize, FILT_SMEM);
    cudaFuncSetAttribute((const void*)k_gfused<true, false>,
                         cudaFuncAttributeMaxDynamicSharedMemorySize, GF_SMEM);
    cudaFuncSetAttribute((const void*)k_gfused<false, true>,
                         cudaFuncAttributeMaxDynamicSharedMemorySize, GF_SMEM);

    // one-time (per launch) prep
    k_wprep<<<NBLK + 50, 256>>>(mw1, mw2, emb, cl1);          // weights + embx + zero cnt
    k_embed<<<(NODES * HIDC + 255) / 256, 256>>>(z, emb, col); // h, x0 gather, CSR count
    k_scan<<<1, 1024>>>();
    k_fill<<<(EDGES + 255) / 256, 256>>>(pos, row, col);
    {
        dim3 tg(TROWS / 128, NBLK);
        k_tbuild<<<tg, 256, FILT_SMEM>>>(mb1, mb2);
    }

    const int gfgrid = (NODES + NPC - 1) / NPC;          // 139 <= 148: one wave
    const int mgrid  = (NODES + 7) / 8;

    for (int k = 0; k < NBLK; k++) {
        k_msg<<<mgrid, 256>>>(k);
        if (k < NBLK - 1) {
            k_gfused<true, false><<<gfgrid, 512, GF_SMEM>>>(
                cl2 + k * HIDC * HIDC, cl2b + k * HIDC,
                lw  + k * HIDC * HIDC, lb   + k * HIDC,
                cl1 + (k + 1) * HIDC * HIDC,
                nullptr, nullptr, nullptr, nullptr, nullptr);
        } else {
            k_gfused<false, true><<<gfgrid, 512, GF_SMEM>>>(
                cl2 + k * HIDC * HIDC, cl2b + k * HIDC,
                lw  + k * HIDC * HIDC, lb   + k * HIDC,
                nullptr, ow1, ob1, ow2, ob2, out);
        }
    }
}

// round 17
// speedup vs baseline: 1.3758x; 1.0001x over previous
#include <cuda_runtime.h>
#include <cuda_fp16.h>
#include <cuda_bf16.h>
#include <cstdint>

#define NODES   10000
#define EDGES   320000
#define HIDC    128
#define NGAUSS  50
#define NBLK    6

#define NPC     72     // nodes per CTA in fused GEMM kernel (512 thr, 8 grp x 9)
#define GNP     9      // nodes per thread-group

#define GDELTA  (10.0f / 49.0f)
#define GCOEFF  (-0.5f / (GDELTA * GDELTA))

#define TROWS   3072                     // filter table rows
#define DMAX    8.66025404f              // max possible d (box 5^3)
#define TSCALE  ((TROWS - 1) / DMAX)
#define DSTEP   (DMAX / (TROWS - 1))

// ---------------- scratch (device globals; no runtime allocation) ----------
__device__ float  g_h[NODES * HIDC];
__device__ __align__(16) __half g_xh[NODES * HIDC];   // x in fp16 (message path)
__device__ float  g_agg[NODES * HIDC];
__device__ float  g_embx[100 * HIDC];                 // emb @ cl1[0]

// CSR by target node + per-edge interp metadata
__device__ int  g_cnt[NODES];
__device__ int  g_rank[EDGES];
__device__ int  g_ptr[NODES + 1];
__device__ __align__(16) int4 g_meta[EDGES];   // {row, tbase, w0_bits, w1_bits}

// filter tables in fp16: W_k(d) on TROWS points, [TROWS][128] per block
__device__ __align__(16) __half g_tableh[NBLK][TROWS * HIDC];

// pre-split bf16 hi/lo weight images, padded row-major [ch][Kpad]
__device__ __align__(16) uint32_t g_w1h[NBLK][4608];
__device__ __align__(16) uint32_t g_w1l[NBLK][4608];
__device__ __align__(16) uint32_t g_w2h[NBLK][8704];
__device__ __align__(16) uint32_t g_w2l[NBLK][8704];

// ---------------- helpers ---------------------------------------------------
using ull = unsigned long long;

__device__ __forceinline__ uint32_t smem_u32(const void* p) {
    uint32_t a;
    asm("{ .reg .u64 t; cvta.to.shared.u64 t, %1; cvt.u32.u64 %0, t; }" : "=r"(a) : "l"(p));
    return a;
}
#define CP16(s, g) asm volatile("cp.async.cg.shared.global [%0], [%1], 16;" :: "r"(s), "l"(g))
#define CP_COMMIT() asm volatile("cp.async.commit_group;" ::: "memory")
#define CP_WAIT(n)  asm volatile("cp.async.wait_group %0;" :: "n"(n) : "memory")

__device__ __forceinline__ void ldsm_x4(uint32_t* r, uint32_t addr) {
    asm volatile("ldmatrix.sync.aligned.m8n8.x4.shared.b16 {%0,%1,%2,%3}, [%4];"
                 : "=r"(r[0]), "=r"(r[1]), "=r"(r[2]), "=r"(r[3]) : "r"(addr));
}
__device__ __forceinline__ void ldsm_x2(uint32_t* r, uint32_t addr) {
    asm volatile("ldmatrix.sync.aligned.m8n8.x2.shared.b16 {%0,%1}, [%2];"
                 : "=r"(r[0]), "=r"(r[1]) : "r"(addr));
}
__device__ __forceinline__ void mma_bf16(float* c, const uint32_t* a, const uint32_t* b) {
    asm volatile("mma.sync.aligned.m16n8k16.row.col.f32.bf16.bf16.f32 "
                 "{%0,%1,%2,%3}, {%4,%5,%6,%7}, {%8,%9}, {%0,%1,%2,%3};"
                 : "+f"(c[0]), "+f"(c[1]), "+f"(c[2]), "+f"(c[3])
                 : "r"(a[0]), "r"(a[1]), "r"(a[2]), "r"(a[3]), "r"(b[0]), "r"(b[1]));
}
__device__ __forceinline__ uint32_t bfpair(float f0, float f1) {
    uint32_t r;
    asm("cvt.rn.bf16x2.f32 %0, %1, %2;" : "=r"(r) : "f"(f1), "f"(f0));
    return r;
}
__device__ __forceinline__ void bfsplit(float f0, float f1, uint32_t& hi, uint32_t& lo) {
    hi = bfpair(f0, f1);
    float h0 = __uint_as_float(hi << 16);
    float h1 = __uint_as_float(hi & 0xFFFF0000u);
    lo = bfpair(f0 - h0, f1 - h1);
}
__device__ __forceinline__ float sspf(float v) {
    float t, u;
    asm("ex2.approx.f32 %0, %1;" : "=f"(t) : "f"(v * 1.4426950408889634f));
    asm("lg2.approx.f32 %0, %1;" : "=f"(u) : "f"(fmaf(0.5f, t, 0.5f)));
    return 0.6931471805599453f * u;
}
__device__ __forceinline__ ull pack2(float a, float b) {
    ull r; asm("mov.b64 %0, {%1, %2};" : "=l"(r) : "f"(a), "f"(b)); return r;
}
__device__ __forceinline__ void unpack2(ull v, float& a, float& b) {
    asm("mov.b64 {%0, %1}, %2;" : "=f"(a), "=f"(b) : "l"(v));
}
__device__ __forceinline__ ull fma2(ull a, ull b, ull c) {
    ull r; asm("fma.rn.f32x2 %0, %1, %2, %3;" : "=l"(r) : "l"(a), "l"(b), "l"(c));
    return r;
}

// ---------------- weight prep + zero CSR counters + parallel embx -----------
// grid = NBLK + 50. Blocks 0..5: filter weights. Blocks 6..55: embx (2 rows each).
__global__ void k_wprep(const float* __restrict__ mw1, const float* __restrict__ mw2,
                        const float* __restrict__ emb, const float* __restrict__ cl1) {
    const int k = blockIdx.x;
    for (int i = blockIdx.x * blockDim.x + threadIdx.x; i < NODES; i += gridDim.x * blockDim.x)
        g_cnt[i] = 0;
    if (k >= NBLK) {
        int r = 2 * (k - NBLK) + (threadIdx.x >> 7);
        int c = threadIdx.x & 127;
        float s = 0.f;
        #pragma unroll 8
        for (int kk = 0; kk < HIDC; kk++) s += emb[r * HIDC + kk] * cl1[kk * HIDC + c];
        g_embx[r * HIDC + c] = s;
        return;
    }
    const float* w1 = mw1 + k * NGAUSS * HIDC;
    const float* w2 = mw2 + k * HIDC * HIDC;
    for (int i = threadIdx.x; i < 4608; i += blockDim.x) {
        int c = i / 36, kk = (i % 36) * 2;
        float v0 = (kk     < NGAUSS) ? w1[kk * HIDC + c]       : 0.f;
        float v1 = (kk + 1 < NGAUSS) ? w1[(kk + 1) * HIDC + c] : 0.f;
        uint32_t hi, lo; bfsplit(v0, v1, hi, lo);
        g_w1h[k][i] = hi; g_w1l[k][i] = lo;
    }
    for (int i = threadIdx.x; i < 8704; i += blockDim.x) {
        int c = i / 68, kk = (i % 68) * 2;
        float v0 = (kk     < HIDC) ? w2[kk * HIDC + c]       : 0.f;
        float v1 = (kk + 1 < HIDC) ? w2[(kk + 1) * HIDC + c] : 0.f;
        uint32_t hi, lo; bfsplit(v0, v1, hi, lo);
        g_w2h[k][i] = hi; g_w2l[k][i] = lo;
    }
}

// ---------------- embedding gather + CSR count + x0 gather ------------------
__global__ void k_embed(const int* __restrict__ z, const float* __restrict__ emb,
                        const int* __restrict__ col) {
    int i = blockIdx.x * blockDim.x + threadIdx.x;
    if (i < EDGES) g_rank[i] = atomicAdd(&g_cnt[col[i]], 1);
    if (i >= NODES * HIDC) return;
    int zi = z[i >> 7] * HIDC + (i & 127);
    g_h[i]  = emb[zi];
    g_xh[i] = __float2half(g_embx[zi]);
}

// ---------------- CSR scan (shuffle-based, 2 barriers) -----------------------
__global__ void k_scan() {   // single block, 1024 threads, chunk=10
    __shared__ int ws[32];
    const int t   = threadIdx.x;
    const int lan = t & 31;
    const int wd  = t >> 5;
    const int base = t * 10;
    int local[10];
    int sum = 0;
    #pragma unroll
    for (int i = 0; i < 10; i++) {
        int idx = base + i;
        local[i] = (idx < NODES) ? g_cnt[idx] : 0;
        sum += local[i];
    }
    // inclusive warp scan of per-thread sums
    int inc = sum;
    #pragma unroll
    for (int off = 1; off < 32; off <<= 1) {
        int v = __shfl_up_sync(0xffffffffu, inc, off);
        if (lan >= off) inc += v;
    }
    if (lan == 31) ws[wd] = inc;
    __syncthreads();
    if (wd == 0) {
        int v = ws[lan];
        int winc = v;
        #pragma unroll
        for (int off = 1; off < 32; off <<= 1) {
            int u = __shfl_up_sync(0xffffffffu, winc, off);
            if (lan >= off) winc += u;
        }
        ws[lan] = winc;
    }
    __syncthreads();
    int run = (wd > 0 ? ws[wd - 1] : 0) + (inc - sum);   // exclusive prefix
    #pragma unroll
    for (int i = 0; i < 10; i++) {
        int idx = base + i;
        if (idx < NODES) { g_ptr[idx] = run; run += local[i]; }
    }
    if (t == 1023) g_ptr[NODES] = ws[31];
}
__global__ void k_fill(const float* __restrict__ pos,
                       const int* __restrict__ row, const int* __restrict__ col) {
    int e = blockIdx.x * blockDim.x + threadIdx.x;
    if (e >= EDGES) return;
    int r = row[e], c = col[e];
    float dx = pos[r * 3 + 0] - pos[c * 3 + 0];
    float dy = pos[r * 3 + 1] - pos[c * 3 + 1];
    float dz = pos[r * 3 + 2] - pos[c * 3 + 2];
    float d = sqrtf(dx * dx + dy * dy + dz * dz);
    float C = 0.5f * (cosf(d * (3.14159265358979323846f / 10.0f)) + 1.0f);
    int pos_ = g_ptr[c] + g_rank[e];
    float fidx = d * TSCALE;
    int tb = (int)fidx;
    if (tb > TROWS - 2) tb = TROWS - 2;
    float fr = fidx - (float)tb;
    int4 m;
    m.x = r;
    m.y = tb;
    m.z = __float_as_int((1.0f - fr) * C);
    m.w = __float_as_int(fr * C);
    g_meta[pos_] = m;
}

// ---------------- table build: MMA filter MLP, 512 threads split-M -----------
// 16 warps: wg = wid>>3 owns row-half (64 rows), band = wid&7 owns 16 channels.
#define S_W1H 0
#define S_W1L 18432
#define S_W2H 36864
#define S_W2L 71680
#define S_AH  106496
#define S_AL  141312
#define FILT_SMEM 176128

__global__ void __launch_bounds__(512, 1)
k_tbuild(const float* __restrict__ mb1, const float* __restrict__ mb2) {
    extern __shared__ __align__(16) unsigned char sraw[];
    const uint32_t sb = smem_u32(sraw);
    const int tid  = threadIdx.x;
    const int wid  = tid >> 5;
    const int lan  = tid & 31;
    const int wg   = wid >> 3;      // 0/1: row half
    const int band = wid & 7;       // 16-channel band
    const int kblk = blockIdx.y;
    const int e0   = blockIdx.x * 128;
    const float* b1g = mb1 + kblk * HIDC;
    const float* b2g = mb2 + kblk * HIDC;

    {
        const int4* s1h = (const int4*)g_w1h[kblk];
        const int4* s1l = (const int4*)g_w1l[kblk];
        const int4* s2h = (const int4*)g_w2h[kblk];
        const int4* s2l = (const int4*)g_w2l[kblk];
        int4* d1h = (int4*)(sraw + S_W1H);
        int4* d1l = (int4*)(sraw + S_W1L);
        int4* d2h = (int4*)(sraw + S_W2H);
        int4* d2l = (int4*)(sraw + S_W2L);
        #pragma unroll 2
        for (int i = tid; i < 1152; i += 512) { d1h[i] = s1h[i]; d1l[i] = s1l[i]; }
        #pragma unroll 4
        for (int i = tid; i < 2176; i += 512) { d2h[i] = s2h[i]; d2l[i] = s2l[i]; }
    }

    for (int i = tid; i < 128 * 36; i += 512) {
        int e = i / 36, kk = (i % 36) * 2;
        float d = (float)(e0 + e) * DSTEP;
        float v0 = 0.f, v1 = 0.f;
        if (kk < NGAUSS)     { float dd = d - (float)kk * GDELTA;       v0 = __expf(GCOEFF * dd * dd); }
        if (kk + 1 < NGAUSS) { float dd = d - (float)(kk + 1) * GDELTA; v1 = __expf(GCOEFF * dd * dd); }
        uint32_t hi, lo; bfsplit(v0, v1, hi, lo);
        *(uint32_t*)(sraw + S_AH + e * 144 + kk * 2) = hi;
        *(uint32_t*)(sraw + S_AL + e * 144 + kk * 2) = lo;
    }
    __syncthreads();

    // fragment address components (row half offset wg*64 baked into A offsets)
    const uint32_t aoff1 = (wg * 64 + (lan & 15)) * 144 + (lan >> 4) * 16;
    const uint32_t boff1 = (band * 16 + (lan & 7)) * 144 + ((lan >> 3) & 1) * 16;
    const uint32_t aoff2 = (wg * 64 + (lan & 15)) * 272 + (lan >> 4) * 16;
    const uint32_t boff2 = (band * 16 + (lan & 7)) * 272 + ((lan >> 3) & 1) * 16;

    float acc[4][2][4];

    // layer 1 (4 m-tiles per warp)
    #pragma unroll
    for (int mt = 0; mt < 4; mt++)
        #pragma unroll
        for (int nt = 0; nt < 2; nt++)
            #pragma unroll
            for (int i = 0; i < 4; i++) acc[mt][nt][i] = 0.f;
    {
        const uint32_t ab[3] = { sb + S_AH + aoff1, sb + S_AH + aoff1, sb + S_AL + aoff1 };
        const uint32_t bb[3] = { sb + S_W1H + boff1, sb + S_W1L + boff1, sb + S_W1H + boff1 };
        #pragma unroll 1
        for (int t = 0; t < 3; t++) {
            #pragma unroll 1
            for (int ks = 0; ks < 4; ks++) {
                uint32_t bf0[2], bf1[2];
                ldsm_x2(bf0, bb[t] + ks * 32);
                ldsm_x2(bf1, bb[t] + 8 * 144 + ks * 32);
                #pragma unroll
                for (int mt = 0; mt < 4; mt++) {
                    uint32_t af[4];
                    ldsm_x4(af, ab[t] + mt * (16 * 144) + ks * 32);
                    mma_bf16(acc[mt][0], af, bf0);
                    mma_bf16(acc[mt][1], af, bf1);
                }
            }
        }
    }
    __syncthreads();

    // epilogue 1: ssp(acc + b1) -> A2 hi/lo [128][136]
    {
        const int ch0 = band * 16 + (lan & 3) * 2;
        const float bA0 = b1g[ch0],     bA1 = b1g[ch0 + 1];
        const float bA2 = b1g[ch0 + 8], bA3 = b1g[ch0 + 9];
        #pragma unroll
        for (int mt = 0; mt < 4; mt++) {
            int er = wg * 64 + mt * 16 + (lan >> 2);
            uint32_t hi, lo;
            float v0 = sspf(acc[mt][0][0] + bA0), v1 = sspf(acc[mt][0][1] + bA1);
            bfsplit(v0, v1, hi, lo);
            *(uint32_t*)(sraw + S_AH + er * 272 + ch0 * 2) = hi;
            *(uint32_t*)(sraw + S_AL + er * 272 + ch0 * 2) = lo;
            float v2 = sspf(acc[mt][0][2] + bA0), v3 = sspf(acc[mt][0][3] + bA1);
            bfsplit(v2, v3, hi, lo);
            *(uint32_t*)(sraw + S_AH + (er + 8) * 272 + ch0 * 2) = hi;
            *(uint32_t*)(sraw + S_AL + (er + 8) * 272 + ch0 * 2) = lo;
            float v4 = sspf(acc[mt][1][0] + bA2), v5 = sspf(acc[mt][1][1] + bA3);
            bfsplit(v4, v5, hi, lo);
            *(uint32_t*)(sraw + S_AH + er * 272 + (ch0 + 8) * 2) = hi;
            *(uint32_t*)(sraw + S_AL + er * 272 + (ch0 + 8) * 2) = lo;
            float v6 = sspf(acc[mt][1][2] + bA2), v7 = sspf(acc[mt][1][3] + bA3);
            bfsplit(v6, v7, hi, lo);
            *(uint32_t*)(sraw + S_AH + (er + 8) * 272 + (ch0 + 8) * 2) = hi;
            *(uint32_t*)(sraw + S_AL + (er + 8) * 272 + (ch0 + 8) * 2) = lo;
        }
    }
    __syncthreads();

    // layer 2
    #pragma unroll
    for (int mt = 0; mt < 4; mt++)
        #pragma unroll
        for (int nt = 0; nt < 2; nt++)
            #pragma unroll
            for (int i = 0; i < 4; i++) acc[mt][nt][i] = 0.f;
    {
        const uint32_t ab[3] = { sb + S_AH + aoff2, sb + S_AH + aoff2, sb + S_AL + aoff2 };
        const uint32_t bb[3] = { sb + S_W2H + boff2, sb + S_W2L + boff2, sb + S_W2H + boff2 };
        #pragma unroll 1
        for (int t = 0; t < 3; t++) {
            #pragma unroll 1
            for (int ks = 0; ks < 8; ks++) {
                uint32_t bf0[2], bf1[2];
                ldsm_x2(bf0, bb[t] + ks * 32);
                ldsm_x2(bf1, bb[t] + 8 * 272 + ks * 32);
                #pragma unroll
                for (int mt = 0; mt < 4; mt++) {
                    uint32_t af[4];
                    ldsm_x4(af, ab[t] + mt * (16 * 272) + ks * 32);
                    mma_bf16(acc[mt][0], af, bf0);
                    mma_bf16(acc[mt][1], af, bf1);
                }
            }
        }
    }

    // epilogue 2: fp16 table
    {
        __half2* tbl = (__half2*)g_tableh[kblk];
        const int ch0 = band * 16 + (lan & 3) * 2;
        const int cp  = ch0 >> 1;
        const float bB0 = b2g[ch0],     bB1 = b2g[ch0 + 1];
        const float bB2 = b2g[ch0 + 8], bB3 = b2g[ch0 + 9];
        #pragma unroll
        for (int mt = 0; mt < 4; mt++) {
            int r0 = e0 + wg * 64 + mt * 16 + (lan >> 2);
            int r1 = r0 + 8;
            tbl[r0 * 64 + cp]     = __floats2half2_rn(acc[mt][0][0] + bB0, acc[mt][0][1] + bB1);
            tbl[r1 * 64 + cp]     = __floats2half2_rn(acc[mt][0][2] + bB0, acc[mt][0][3] + bB1);
            tbl[r0 * 64 + cp + 4] = __floats2half2_rn(acc[mt][1][0] + bB2, acc[mt][1][1] + bB3);
            tbl[r1 * 64 + cp + 4] = __floats2half2_rn(acc[mt][1][2] + bB2, acc[mt][1][3] + bB3);
        }
    }
}

// ---------------- message + aggregate: CSR gather, fp16 table lerp ----------
__global__ void __launch_bounds__(256)
k_msg(int kblk) {
    const int wid = threadIdx.x >> 5;
    const int lan = threadIdx.x & 31;
    const int n = blockIdx.x * 8 + wid;
    if (n >= NODES) return;
    const int s = g_ptr[n], e = g_ptr[n + 1];
    const uint2* __restrict__ T = (const uint2*)g_tableh[kblk];
    const uint2* __restrict__ X = (const uint2*)g_xh;
    float4 acc = make_float4(0.f, 0.f, 0.f, 0.f);
    #pragma unroll 2
    for (int j = s; j < e; j++) {
        const int4 m = __ldg(&g_meta[j]);
        const float w0 = __int_as_float(m.z);
        const float w1 = __int_as_float(m.w);
        const uint2 xr = X[m.x * 32 + lan];
        const uint2 t0 = T[m.y * 32 + lan];
        const uint2 t1 = T[m.y * 32 + 32 + lan];
        float2 xa = __half22float2(*(const __half2*)&xr.x);
        float2 xb = __half22float2(*(const __half2*)&xr.y);
        float2 a0 = __half22float2(*(const __half2*)&t0.x);
        float2 a1 = __half22float2(*(const __half2*)&t0.y);
        float2 b0 = __half22float2(*(const __half2*)&t1.x);
        float2 b1 = __half22float2(*(const __half2*)&t1.y);
        acc.x += xa.x * (a0.x * w0 + b0.x * w1);
        acc.y += xa.y * (a0.y * w0 + b0.y * w1);
        acc.z += xb.x * (a1.x * w0 + b1.x * w1);
        acc.w += xb.y * (a1.y * w0 + b1.y * w1);
    }
    ((float4*)g_agg)[n * 32 + lan] = acc;
}

// ------ fused node GEMMs, cp.async double-buffered, SINGLE WAVE (139 CTAs) ---
// Phases: A: mid = ssp(agg@W2+b2); B: h += mid@Wl+bl;
//   DO_C:   C: xh = h_new @ Wc (fp16)
//   DO_OUT: D: out = ssp(h_new@ow1+ob1)@ow2 + ob2
#define GF_SMEM ((16384 * 2 + NPC * HIDC) * 4)   // 167936 B

template <bool DO_C, bool DO_OUT>
__global__ void __launch_bounds__(512, 1)
k_gfused(const float* __restrict__ W2, const float* __restrict__ b2v,
         const float* __restrict__ Wl, const float* __restrict__ blv,
         const float* __restrict__ Wc,
         const float* __restrict__ ow1, const float* __restrict__ ob1,
         const float* __restrict__ ow2, const float* __restrict__ ob2,
         float* __restrict__ out) {
    extern __shared__ __align__(16) unsigned char sraw[];
    float* W0   = (float*)sraw;                     // 64 KB
    float* W1   = W0 + 16384;                       // 64 KB
    float* data = W1 + 16384;                       // 36 KB
    const uint32_t sW0 = smem_u32(W0);
    const uint32_t sW1 = smem_u32(W1);
    const uint32_t sD  = smem_u32(data);

    const int tid = threadIdx.x;
    const int f2  = tid & 63;
    const int grp = tid >> 6;       // 0..7
    const int n0  = blockIdx.x * NPC;
    const int nb  = grp * GNP;

    // group 0: W2 + agg tile
    {
        uint64_t gw = __cvta_generic_to_global(W2);
        #pragma unroll
        for (int i = tid; i < 4096; i += 512) CP16(sW0 + i * 16, gw + i * 16);
        uint64_t ga = __cvta_generic_to_global(g_agg);
        for (int i = tid; i < NPC * 32; i += 512) {
            int n = n0 + (i >> 5);
            int nc = (n < NODES) ? n : NODES - 1;
            CP16(sD + i * 16, ga + (uint64_t)(nc * 32 + (i & 31)) * 16);
        }
    }
    CP_COMMIT();
    // group 1: Wl
    {
        uint64_t gw = __cvta_generic_to_global(Wl);
        #pragma unroll
        for (int i = tid; i < 4096; i += 512) CP16(sW1 + i * 16, gw + i * 16);
    }
    CP_COMMIT();

    const float b2a = b2v[f2],      b2b = b2v[f2 + 64];
    const float bla = blv[f2],      blb = blv[f2 + 64];

    CP_WAIT(1);
    __syncthreads();

    // ---- phase A: mid = ssp(agg @ W2 + b2) ----
    float mida[GNP], midb[GNP];
    {
        ull acc0[GNP], acc1[GNP];
        #pragma unroll
        for (int e = 0; e < GNP; e++) { acc0[e] = pack2(b2a, 0.f); acc1[e] = pack2(b2b, 0.f); }
        #pragma unroll 1
        for (int c = 0; c < HIDC; c += 4) {
            ull wa01 = pack2(W0[c * HIDC + f2],       W0[(c + 1) * HIDC + f2]);
            ull wa23 = pack2(W0[(c + 2) * HIDC + f2], W0[(c + 3) * HIDC + f2]);
            ull wb01 = pack2(W0[c * HIDC + f2 + 64],       W0[(c + 1) * HIDC + f2 + 64]);
            ull wb23 = pack2(W0[(c + 2) * HIDC + f2 + 64], W0[(c + 3) * HIDC + f2 + 64]);
            #pragma unroll
            for (int e = 0; e < GNP; e++) {
                ulonglong2 hv = *(const ulonglong2*)&data[(nb + e) * HIDC + c];
                acc0[e] = fma2(hv.x, wa01, acc0[e]);
                acc0[e] = fma2(hv.y, wa23, acc0[e]);
                acc1[e] = fma2(hv.x, wb01, acc1[e]);
                acc1[e] = fma2(hv.y, wb23, acc1[e]);
            }
        }
        #pragma unroll
        for (int e = 0; e < GNP; e++) {
            float a, b;
            unpack2(acc0[e], a, b); mida[e] = sspf(a + b);
            unpack2(acc1[e], a, b); midb[e] = sspf(a + b);
        }
    }
    __syncthreads();

    // data = mid ; prefetch next matrix -> W0
    #pragma unroll
    for (int e = 0; e < GNP; e++) {
        data[(nb + e) * HIDC + f2]      = mida[e];
        data[(nb + e) * HIDC + f2 + 64] = midb[e];
    }
    if (DO_C) {
        uint64_t gw = __cvta_generic_to_global(Wc);
        #pragma unroll
        for (int i = tid; i < 4096; i += 512) CP16(sW0 + i * 16, gw + i * 16);
        CP_COMMIT();
        CP_WAIT(1);
    } else if (DO_OUT) {
        uint64_t gw = __cvta_generic_to_global(ow1);   // 128x64 = 2048 int4
        #pragma unroll
        for (int i = tid; i < 2048; i += 512) CP16(sW0 + i * 16, gw + i * 16);
        CP_COMMIT();
        CP_WAIT(1);
    } else {
        CP_WAIT(0);
    }
    __syncthreads();

    // ---- phase B: h_new = h + mid @ Wl + bl ----
    float hna[GNP], hnb[GNP];
    {
        ull acc0[GNP], acc1[GNP];
        #pragma unroll
        for (int e = 0; e < GNP; e++) { acc0[e] = pack2(bla, 0.f); acc1[e] = pack2(blb, 0.f); }
        #pragma unroll 1
        for (int c = 0; c < HIDC; c += 4) {
            ull wa01 = pack2(W1[c * HIDC + f2],       W1[(c + 1) * HIDC + f2]);
            ull wa23 = pack2(W1[(c + 2) * HIDC + f2], W1[(c + 3) * HIDC + f2]);
            ull wb01 = pack2(W1[c * HIDC + f2 + 64],       W1[(c + 1) * HIDC + f2 + 64]);
            ull wb23 = pack2(W1[(c + 2) * HIDC + f2 + 64], W1[(c + 3) * HIDC + f2 + 64]);
            #pragma unroll
            for (int e = 0; e < GNP; e++) {
                ulonglong2 hv = *(const ulonglong2*)&data[(nb + e) * HIDC + c];
                acc0[e] = fma2(hv.x, wa01, acc0[e]);
                acc0[e] = fma2(hv.y, wa23, acc0[e]);
                acc1[e] = fma2(hv.x, wb01, acc1[e]);
                acc1[e] = fma2(hv.y, wb23, acc1[e]);
            }
        }
        #pragma unroll
        for (int e = 0; e < GNP; e++) {
            int n = n0 + nb + e;
            float a, b;
            unpack2(acc0[e], a, b);
            float h0 = (n < NODES) ? g_h[n * HIDC + f2] : 0.f;
            hna[e] = h0 + a + b;
            unpack2(acc1[e], a, b);
            float h1 = (n < NODES) ? g_h[n * HIDC + f2 + 64] : 0.f;
            hnb[e] = h1 + a + b;
            if (n < NODES) {
                g_h[n * HIDC + f2]      = hna[e];
                g_h[n * HIDC + f2 + 64] = hnb[e];
            }
        }
    }
    if (!DO_C && !DO_OUT) return;

    __syncthreads();    // phase B reads of data done

    // data = h_new
    #pragma unroll
    for (int e = 0; e < GNP; e++) {
        data[(nb + e) * HIDC + f2]      = hna[e];
        data[(nb + e) * HIDC + f2 + 64] = hnb[e];
    }
    CP_WAIT(0);
    __syncthreads();

    if (DO_C) {
        // ---- phase C: xh = h_new @ Wc (fp16) ----
        ull acc0[GNP], acc1[GNP];
        #pragma unroll
        for (int e = 0; e < GNP; e++) { acc0[e] = pack2(0.f, 0.f); acc1[e] = pack2(0.f, 0.f); }
        #pragma unroll 1
        for (int c = 0; c < HIDC; c += 4) {
            ull wa01 = pack2(W0[c * HIDC + f2],       W0[(c + 1) * HIDC + f2]);
            ull wa23 = pack2(W0[(c + 2) * HIDC + f2], W0[(c + 3) * HIDC + f2]);
            ull wb01 = pack2(W0[c * HIDC + f2 + 64],       W0[(c + 1) * HIDC + f2 + 64]);
            ull wb23 = pack2(W0[(c + 2) * HIDC + f2 + 64], W0[(c + 3) * HIDC + f2 + 64]);
            #pragma unroll
            for (int e = 0; e < GNP; e++) {
                ulonglong2 hv = *(const ulonglong2*)&data[(nb + e) * HIDC + c];
                acc0[e] = fma2(hv.x, wa01, acc0[e]);
                acc0[e] = fma2(hv.y, wa23, acc0[e]);
                acc1[e] = fma2(hv.x, wb01, acc1[e]);
                acc1[e] = fma2(hv.y, wb23, acc1[e]);
            }
        }
        #pragma unroll
        for (int e = 0; e < GNP; e++) {
            int n = n0 + nb + e;
            if (n < NODES) {
                float a, b;
                unpack2(acc0[e], a, b);
                g_xh[n * HIDC + f2]      = __float2half(a + b);
                unpack2(acc1[e], a, b);
                g_xh[n * HIDC + f2 + 64] = __float2half(a + b);
            }
        }
    }

    if (DO_OUT) {
        // ---- phase D: out = ssp(h_new @ ow1 + ob1) @ ow2 + ob2 ----
        const float ob1v = ob1[f2];
        const float ow2v = ow2[f2];
        ull accO[GNP];
        #pragma unroll
        for (int e = 0; e < GNP; e++) accO[e] = pack2(ob1v, 0.f);
        #pragma unroll 1
        for (int c = 0; c < HIDC; c += 4) {
            ull w01 = pack2(W0[c * 64 + f2],       W0[(c + 1) * 64 + f2]);
            ull w23 = pack2(W0[(c + 2) * 64 + f2], W0[(c + 3) * 64 + f2]);
            #pragma unroll
            for (int e = 0; e < GNP; e++) {
                ulonglong2 hv = *(const ulonglong2*)&data[(nb + e) * HIDC + c];
                accO[e] = fma2(hv.x, w01, accO[e]);
                accO[e] = fma2(hv.y, w23, accO[e]);
            }
        }
        float s[GNP];
        #pragma unroll
        for (int e = 0; e < GNP; e++) {
            float a, b; unpack2(accO[e], a, b);
            s[e] = sspf(a + b) * ow2v;
        }
        #pragma unroll
        for (int off = 16; off > 0; off >>= 1)
            #pragma unroll
            for (int e = 0; e < GNP; e++)
                s[e] += __shfl_down_sync(0xffffffffu, s[e], off);
        __syncthreads();
        float* part = data;   // reuse: [16 warps][GNP]
        const int wid = tid >> 5;
        if ((tid & 31) == 0) {
            #pragma unroll
            for (int e = 0; e < GNP; e++) part[wid * GNP + e] = s[e];
        }
        __syncthreads();
        if (tid < NPC) {
            int g = tid / GNP, e = tid % GNP;
            int n = n0 + tid;
            if (n < NODES)
                out[n] = part[(g * 2) * GNP + e] + part[(g * 2 + 1) * GNP + e] + ob2[0];
        }
    }
}

// ---------------- launcher ---------------------------------------------------
extern "C" void kernel_launch(void* const* d_in, const int* in_sizes, int n_in,
                              void* d_out, int out_size) {
    const int*   z    = (const int*)d_in[0];
    const float* pos  = (const float*)d_in[1];
    const int*   ei   = (const int*)d_in[2];
    const float* emb  = (const float*)d_in[3];
    const float* mw1  = (const float*)d_in[4];
    const float* mb1  = (const float*)d_in[5];
    const float* mw2  = (const float*)d_in[6];
    const float* mb2  = (const float*)d_in[7];
    const float* cl1  = (const float*)d_in[8];
    const float* cl2  = (const float*)d_in[9];
    const float* cl2b = (const float*)d_in[10];
    const float* lw   = (const float*)d_in[11];
    const float* lb   = (const float*)d_in[12];
    const float* ow1  = (const float*)d_in[13];
    const float* ob1  = (const float*)d_in[14];
    const float* ow2  = (const float*)d_in[15];
    const float* ob2  = (const float*)d_in[16];
    float* out = (float*)d_out;

    const int* row = ei;
    const int* col = ei + EDGES;

    cudaFuncSetAttribute(k_tbuild, cudaFuncAttributeMaxDynamicSharedMemorySize, FILT_SMEM);
    cudaFuncSetAttribute((const void*)k_gfused<true, false>,
                         cudaFuncAttributeMaxDynamicSharedMemorySize, GF_SMEM);
    cudaFuncSetAttribute((const void*)k_gfused<false, true>,
                         cudaFuncAttributeMaxDynamicSharedMemorySize, GF_SMEM);

    // one-time (per launch) prep
    k_wprep<<<NBLK + 50, 256>>>(mw1, mw2, emb, cl1);          // weights + embx + zero cnt
    k_embed<<<(NODES * HIDC + 255) / 256, 256>>>(z, emb, col); // h, x0 gather, CSR count
    k_scan<<<1, 1024>>>();
    k_fill<<<(EDGES + 255) / 256, 256>>>(pos, row, col);
    {
        dim3 tg(TROWS / 128, NBLK);
        k_tbuild<<<tg, 512, FILT_SMEM>>>(mb1, mb2);
    }

    const int gfgrid = (NODES + NPC - 1) / NPC;          // 139 <= 148: one wave
    const int mgrid  = (NODES + 7) / 8;

    for (int k = 0; k < NBLK; k++) {
        k_msg<<<mgrid, 256>>>(k);
        if (k < NBLK - 1) {
            k_gfused<true, false><<<gfgrid, 512, GF_SMEM>>>(
                cl2 + k * HIDC * HIDC, cl2b + k * HIDC,
                lw  + k * HIDC * HIDC, lb   + k * HIDC,
                cl1 + (k + 1) * HIDC * HIDC,
                nullptr, nullptr, nullptr, nullptr, nullptr);
        } else {
            k_gfused<false, true><<<gfgrid, 512, GF_SMEM>>>(
                cl2 + k * HIDC * HIDC, cl2b + k * HIDC,
                lw  + k * HIDC * HIDC, lb   + k * HIDC,
                nullptr, ow1, ob1, ow2, ob2, out);
        }
    }
}